// round 11
// baseline (speedup 1.0000x reference)
#include <cuda_runtime.h>
#include <cuda_bf16.h>
#include <cstdint>
#include <math.h>

// Problem constants
#define BB 4
#define SS 2048
#define DD 1024
#define HH 16
#define HD 64
#define MTOT (BB*SS)      // 8192
#define NQKV (3*DD)       // 3072
#define NHEADS (BB*HH)    // 64

// Q pre-scale: 1/sqrt(64) * log2(e)  (softmax done in exp2 domain)
#define QSCALE 0.1803368801111204f

// ---------------------------------------------------------------------------
// Scratch (static device globals — allowed)
// ---------------------------------------------------------------------------
__device__ __nv_bfloat16 g_Xh[(size_t)MTOT*DD];
__device__ __nv_bfloat16 g_Xl[(size_t)MTOT*DD];
__device__ __nv_bfloat16 g_WqTh[(size_t)NQKV*DD];
__device__ __nv_bfloat16 g_WqTl[(size_t)NQKV*DD];
__device__ __nv_bfloat16 g_WoTh[(size_t)DD*DD];
__device__ __nv_bfloat16 g_WoTl[(size_t)DD*DD];
__device__ __nv_bfloat16 g_Qh[(size_t)NHEADS*SS*HD];
__device__ __nv_bfloat16 g_Ql[(size_t)NHEADS*SS*HD];
__device__ __nv_bfloat16 g_Kh[(size_t)NHEADS*SS*HD];
__device__ __nv_bfloat16 g_Kl[(size_t)NHEADS*SS*HD];
__device__ __nv_bfloat16 g_Vh[(size_t)NHEADS*SS*HD];
__device__ __nv_bfloat16 g_Vl[(size_t)NHEADS*SS*HD];
__device__ __nv_bfloat16 g_Oh[(size_t)MTOT*DD];
__device__ __nv_bfloat16 g_Ol[(size_t)MTOT*DD];

// ---------------------------------------------------------------------------
// PTX helpers (plain compute_103-compatible: mma.sync / ldmatrix / cp.async)
// ---------------------------------------------------------------------------
__device__ __forceinline__ uint32_t smem_u32(const void* p) {
    uint32_t a;
    asm("{ .reg .u64 t; cvta.to.shared.u64 t, %1; cvt.u32.u64 %0, t; }"
        : "=r"(a) : "l"(p));
    return a;
}
__device__ __forceinline__ void cp16(uint32_t dst, const void* src) {
    asm volatile("cp.async.cg.shared.global [%0], [%1], 16;\n"
                 :: "r"(dst), "l"(src));
}
#define CP_COMMIT() asm volatile("cp.async.commit_group;\n" ::: "memory")
#define CP_WAIT(n)  asm volatile("cp.async.wait_group %0;\n" :: "n"(n) : "memory")

__device__ __forceinline__ void ldsm4(uint32_t* r, uint32_t addr) {
    asm volatile("ldmatrix.sync.aligned.m8n8.x4.shared.b16 {%0,%1,%2,%3}, [%4];\n"
                 : "=r"(r[0]), "=r"(r[1]), "=r"(r[2]), "=r"(r[3]) : "r"(addr));
}
__device__ __forceinline__ void ldsm4t(uint32_t* r, uint32_t addr) {
    asm volatile("ldmatrix.sync.aligned.m8n8.x4.trans.shared.b16 {%0,%1,%2,%3}, [%4];\n"
                 : "=r"(r[0]), "=r"(r[1]), "=r"(r[2]), "=r"(r[3]) : "r"(addr));
}
__device__ __forceinline__ void mma_bf16(float* c, const uint32_t* a,
                                         uint32_t b0, uint32_t b1) {
    asm volatile(
        "mma.sync.aligned.m16n8k16.row.col.f32.bf16.bf16.f32 "
        "{%0,%1,%2,%3}, {%4,%5,%6,%7}, {%8,%9}, {%0,%1,%2,%3};\n"
        : "+f"(c[0]), "+f"(c[1]), "+f"(c[2]), "+f"(c[3])
        : "r"(a[0]), "r"(a[1]), "r"(a[2]), "r"(a[3]), "r"(b0), "r"(b1));
}
__device__ __forceinline__ float ex2(float x) {
    float y;
    asm("ex2.approx.ftz.f32 %0, %1;" : "=f"(y) : "f"(x));
    return y;
}
__device__ __forceinline__ void split2(float x, float y,
                                       __nv_bfloat162& h2, __nv_bfloat162& l2) {
    __nv_bfloat16 hx = __float2bfloat16(x);
    __nv_bfloat16 hy = __float2bfloat16(y);
    h2.x = hx; h2.y = hy;
    l2.x = __float2bfloat16(x - __bfloat162float(hx));
    l2.y = __float2bfloat16(y - __bfloat162float(hy));
}

// ---------------------------------------------------------------------------
// Fused prep: one launch.
// ---------------------------------------------------------------------------
__device__ __forceinline__ void do_transpose_split(
    const float* __restrict__ W, int K, int N, int bx, int by, int tid,
    __nv_bfloat16* __restrict__ Th, __nv_bfloat16* __restrict__ Tl)
{
    __shared__ float t[32][33];
    int nb = bx * 32, kb = by * 32;
    int tx = tid & 31, ty = tid >> 5;
    #pragma unroll
    for (int j = 0; j < 4; j++)
        t[ty + j*8][tx] = W[(size_t)(kb + ty + j*8) * N + nb + tx];
    __syncthreads();
    #pragma unroll
    for (int j = 0; j < 4; j++) {
        int n = nb + ty + j*8;
        float v = t[tx][ty + j*8];
        __nv_bfloat16 h = __float2bfloat16(v);
        Th[(size_t)n * K + kb + tx] = h;
        Tl[(size_t)n * K + kb + tx] = __float2bfloat16(v - __bfloat162float(h));
    }
}

__global__ void __launch_bounds__(256) prep_kernel(
    const float* __restrict__ x, const float* __restrict__ Wqkv,
    const float* __restrict__ Wo)
{
    int bid = blockIdx.x;
    int tid = threadIdx.x;
    if (bid < 8192) {
        size_t i4 = ((size_t)bid * 256 + tid) * 4;
        float4 v = *(const float4*)(x + i4);
        __nv_bfloat162 h0, l0, h1, l1;
        split2(v.x, v.y, h0, l0);
        split2(v.z, v.w, h1, l1);
        *(__nv_bfloat162*)(g_Xh + i4)     = h0;
        *(__nv_bfloat162*)(g_Xh + i4 + 2) = h1;
        *(__nv_bfloat162*)(g_Xl + i4)     = l0;
        *(__nv_bfloat162*)(g_Xl + i4 + 2) = l1;
    } else if (bid < 8192 + 3072) {
        int b = bid - 8192;
        do_transpose_split(Wqkv, DD, NQKV, b % 96, b / 96, tid, g_WqTh, g_WqTl);
    } else {
        int b = bid - 8192 - 3072;
        do_transpose_split(Wo, DD, DD, b % 32, b / 32, tid, g_WoTh, g_WoTl);
    }
}

// ---------------------------------------------------------------------------
// GEMM variant A (NEW, GEMM1): BM=128, BN=256, BK=32, 256 threads, 8 warps
// (2m x 4n), warp tile 64x64 (4 MMA/LDSM), 3 stages (90KB), 1 CTA/SM,
// regs ~200 within the 256-reg cap at 256 threads (no spill).
// Scatter epilogue (mode 0 semantics: +bqkv, Q-scale, split to Q/K/V).
// ---------------------------------------------------------------------------
#define W2PITCH 80
#define W2ASTG (128*W2PITCH)             // 10240
#define W2BSTG (256*W2PITCH)             // 20480
#define SMEM_GEMM2 (3*(W2ASTG+W2BSTG))   // 92160

__global__ void __launch_bounds__(256, 1) gemm_wide_kernel(
    const __nv_bfloat16* __restrict__ Ah, const __nv_bfloat16* __restrict__ Al,
    const __nv_bfloat16* __restrict__ Bh, const __nv_bfloat16* __restrict__ Bl,
    const float* __restrict__ bias)
{
    extern __shared__ char sm[];
    const uint32_t sb = smem_u32(sm);
    const int tid = threadIdx.x, wid = tid >> 5, lane = tid & 31;
    const int wm = wid >> 2, wn = wid & 3;   // 2 x 4 warp grid
    const int m0 = blockIdx.y * 128, n0 = blockIdx.x * 256;

    float acc[4][8][4];
    #pragma unroll
    for (int i = 0; i < 4; i++)
        #pragma unroll
        for (int j = 0; j < 8; j++)
            #pragma unroll
            for (int e = 0; e < 4; e++) acc[i][j][e] = 0.0f;

    // issue one 32-K chunk into stage st: A 2 cp16/thread, B 4 cp16/thread
    #define GW_ISSUE(c, st) do {                                                \
        int _p = (c) >> 5; int _kb = ((c) & 31) * 32;                           \
        const __nv_bfloat16* _Ap = (_p == 1) ? Al : Ah;                         \
        const __nv_bfloat16* _Bp = (_p == 2) ? Bl : Bh;                         \
        uint32_t _da = sb + (st) * W2ASTG;                                      \
        uint32_t _db = sb + 3*W2ASTG + (st) * W2BSTG;                           \
        _Pragma("unroll")                                                       \
        for (int _j = 0; _j < 2; _j++) {                                        \
            int _idx = tid + _j*256;                                            \
            int _row = _idx >> 2, _q = _idx & 3;                                \
            cp16(_da + _row*W2PITCH + _q*16,                                    \
                 _Ap + (size_t)(m0+_row)*DD + _kb + _q*8);                      \
        }                                                                       \
        _Pragma("unroll")                                                       \
        for (int _j = 0; _j < 4; _j++) {                                        \
            int _idx = tid + _j*256;                                            \
            int _row = _idx >> 2, _q = _idx & 3;                                \
            cp16(_db + _row*W2PITCH + _q*16,                                    \
                 _Bp + (size_t)(n0+_row)*DD + _kb + _q*8);                      \
        }                                                                       \
    } while (0)

    GW_ISSUE(0, 0); CP_COMMIT();
    GW_ISSUE(1, 1); CP_COMMIT();

    const int NCH = 96;  // 3072 / 32
    int cur = 0;
    for (int c = 0; c < NCH; c++) {
        CP_WAIT(1);
        __syncthreads();
        int nxt = cur + 2 >= 3 ? cur - 1 : cur + 2;
        if (c + 2 < NCH) GW_ISSUE(c + 2, nxt);
        CP_COMMIT();

        uint32_t da = sb + cur * W2ASTG;
        uint32_t db = sb + 3*W2ASTG + cur * W2BSTG;

        // B fragments: 8 x (n8 x k32)
        uint32_t bfr[8][4];
        #pragma unroll
        for (int nt = 0; nt < 8; nt++)
            ldsm4(bfr[nt], db + (wn*64 + nt*8 + (lane & 7))*W2PITCH + (lane >> 3)*16);

        #pragma unroll
        for (int kk = 0; kk < 2; kk++) {
            uint32_t afr[4][4];
            #pragma unroll
            for (int mt = 0; mt < 4; mt++)
                ldsm4(afr[mt], da + (wm*64 + mt*16 + (lane & 15))*W2PITCH
                               + kk*32 + (lane >> 4)*16);
            #pragma unroll
            for (int mt = 0; mt < 4; mt++)
                #pragma unroll
                for (int nt = 0; nt < 8; nt++)
                    mma_bf16(acc[mt][nt], afr[mt], bfr[nt][kk*2], bfr[nt][kk*2+1]);
        }
        cur = cur + 1 >= 3 ? 0 : cur + 1;
    }

    // ---- epilogue: +bias, Q-scale, split, scatter to Q/K/V ----
    #pragma unroll
    for (int mt = 0; mt < 4; mt++) {
        #pragma unroll
        for (int rr = 0; rr < 2; rr++) {
            int row = wm*64 + mt*16 + (lane >> 2) + rr*8;
            int m = m0 + row;
            int b = m >> 11, s = m & 2047;
            #pragma unroll
            for (int nt = 0; nt < 8; nt++) {
                int col = n0 + wn*64 + nt*8 + 2*(lane & 3);
                float v0 = acc[mt][nt][rr*2]   + bias[col];
                float v1 = acc[mt][nt][rr*2+1] + bias[col+1];
                int h = col / 192;
                int t = col - h*192;
                int which = t >> 6;
                int hd = t & 63;
                if (which == 0) { v0 *= QSCALE; v1 *= QSCALE; }
                __nv_bfloat162 h2, l2;
                split2(v0, v1, h2, l2);
                size_t off = (((size_t)b*HH + h)*SS + s)*HD + hd;
                __nv_bfloat16* dh = (which == 0) ? g_Qh : (which == 1) ? g_Kh : g_Vh;
                __nv_bfloat16* dl = (which == 0) ? g_Ql : (which == 1) ? g_Kl : g_Vl;
                *(__nv_bfloat162*)(dh + off) = h2;
                *(__nv_bfloat162*)(dl + off) = l2;
            }
        }
    }
}

// ---------------------------------------------------------------------------
// GEMM variant B (R6 proven, GEMM2): BM=BN=128, BK=64/stage, 2 CTAs/SM.
// ---------------------------------------------------------------------------
#define GPITCH 144
#define GSTG (128*GPITCH)   // 18432 per operand per stage
#define SMEM_GEMM (6*GSTG)  // 110592

__global__ void __launch_bounds__(256, 2) gemm_ext_kernel(
    const __nv_bfloat16* __restrict__ Ah, const __nv_bfloat16* __restrict__ Al,
    const __nv_bfloat16* __restrict__ Bh, const __nv_bfloat16* __restrict__ Bl,
    const float* __restrict__ bias, float* __restrict__ out)
{
    extern __shared__ char sm[];
    const uint32_t sb = smem_u32(sm);
    const int tid = threadIdx.x, wid = tid >> 5, lane = tid & 31;
    const int wm = wid >> 2, wn = wid & 3;
    const int m0 = blockIdx.y * 128, n0 = blockIdx.x * 128;

    float acc[4][4][4];
    #pragma unroll
    for (int i = 0; i < 4; i++)
        #pragma unroll
        for (int j = 0; j < 4; j++)
            #pragma unroll
            for (int e = 0; e < 4; e++) acc[i][j][e] = 0.0f;

    #define GEMM_ISSUE(c, st) do {                                             \
        int _p = (c) >> 4; int _kb = ((c) & 15) * 64;                          \
        const __nv_bfloat16* _Ap = (_p == 1) ? Al : Ah;                        \
        const __nv_bfloat16* _Bp = (_p == 2) ? Bl : Bh;                        \
        uint32_t _da = sb + (st) * GSTG;                                       \
        uint32_t _db = sb + 3*GSTG + (st) * GSTG;                              \
        _Pragma("unroll")                                                      \
        for (int _j = 0; _j < 4; _j++) {                                       \
            int _idx = tid + _j*256;                                           \
            int _row = _idx >> 3, _q = _idx & 7;                               \
            cp16(_da + _row*GPITCH + _q*16,                                    \
                 _Ap + (size_t)(m0+_row)*DD + _kb + _q*8);                     \
            cp16(_db + _row*GPITCH + _q*16,                                    \
                 _Bp + (size_t)(n0+_row)*DD + _kb + _q*8);                     \
        }                                                                      \
    } while (0)

    GEMM_ISSUE(0, 0); CP_COMMIT();
    GEMM_ISSUE(1, 1); CP_COMMIT();

    const int NCH = 48;
    int cur = 0;
    for (int c = 0; c < NCH; c++) {
        CP_WAIT(1);
        __syncthreads();
        int nxt = cur + 2 >= 3 ? cur - 1 : cur + 2;
        if (c + 2 < NCH) GEMM_ISSUE(c + 2, nxt);
        CP_COMMIT();

        uint32_t da = sb + cur * GSTG;
        uint32_t db = sb + 3*GSTG + cur * GSTG;

        #pragma unroll
        for (int kc2 = 0; kc2 < 2; kc2++) {
            uint32_t bfr[4][4];
            #pragma unroll
            for (int nt = 0; nt < 4; nt++)
                ldsm4(bfr[nt], db + (wn*32 + nt*8 + (lane & 7))*GPITCH
                               + kc2*64 + (lane >> 3)*16);
            #pragma unroll
            for (int kk = 0; kk < 2; kk++) {
                uint32_t afr[4][4];
                #pragma unroll
                for (int mt = 0; mt < 4; mt++)
                    ldsm4(afr[mt], da + (wm*64 + mt*16 + (lane & 15))*GPITCH
                                   + kc2*64 + kk*32 + (lane >> 4)*16);
                #pragma unroll
                for (int mt = 0; mt < 4; mt++)
                    #pragma unroll
                    for (int nt = 0; nt < 4; nt++)
                        mma_bf16(acc[mt][nt], afr[mt], bfr[nt][kk*2], bfr[nt][kk*2+1]);
            }
        }
        cur = cur + 1 >= 3 ? 0 : cur + 1;
    }

    #pragma unroll
    for (int mt = 0; mt < 4; mt++) {
        #pragma unroll
        for (int rr = 0; rr < 2; rr++) {
            int row = wm*64 + mt*16 + (lane >> 2) + rr*8;
            int m = m0 + row;
            #pragma unroll
            for (int nt = 0; nt < 4; nt++) {
                int col = n0 + wn*32 + nt*8 + 2*(lane & 3);
                float2 f2;
                f2.x = acc[mt][nt][rr*2]   + bias[col];
                f2.y = acc[mt][nt][rr*2+1] + bias[col+1];
                *(float2*)&out[(size_t)m*DD + col] = f2;
            }
        }
    }
}

// ---------------------------------------------------------------------------
// Flash attention (R6/R8/R10 proven version) — unchanged.
// ---------------------------------------------------------------------------
#define QPITCH 272
#define VPITCH 144
#define QS_OFF 0
#define KS_OFF 17408
#define KBUF   17408
#define VS_OFF (KS_OFF + 2*KBUF)
#define VBUF   18432
#define PS_OFF (VS_OFF + 2*VBUF)
#define RED_OFF (PS_OFF + 17408)
#define SMEM_ATTN (RED_OFF + 1024)

__global__ void __launch_bounds__(256, 2) attn_kernel()
{
    const int qt = blockIdx.x;
    const int bh = blockIdx.y;
    extern __shared__ char sm[];
    const uint32_t sb = smem_u32(sm);
    const int tid = threadIdx.x, wid = tid >> 5, lane = tid & 31;
    const int wm = wid >> 1, wn = wid & 1;

    const size_t base = (size_t)bh * SS * HD;
    const __nv_bfloat16* Qh = g_Qh + base + (size_t)qt*64*HD;
    const __nv_bfloat16* Ql = g_Ql + base + (size_t)qt*64*HD;
    const __nv_bfloat16* Kh = g_Kh + base;
    const __nv_bfloat16* Kl = g_Kl + base;
    const __nv_bfloat16* Vh = g_Vh + base;
    const __nv_bfloat16* Vl = g_Vl + base;

    #pragma unroll
    for (int j = 0; j < 4; j++) {
        int idx = tid + j*256;
        int row = idx >> 4, q = idx & 15;
        if (q < 8)
            cp16(sb + QS_OFF + row*QPITCH + q*16, Qh + (size_t)row*HD + q*8);
        else
            cp16(sb + QS_OFF + row*QPITCH + 128 + (q-8)*16, Ql + (size_t)row*HD + (q-8)*8);
    }

    #define LOAD_KV(t, buf) do {                                               \
        int _s0 = (t) * 64;                                                    \
        _Pragma("unroll")                                                      \
        for (int j = 0; j < 4; j++) {                                          \
            int _idx = tid + j*256;                                            \
            int _row = _idx >> 4, _q = _idx & 15;                              \
            if (_q < 8)                                                        \
                cp16(sb + KS_OFF + (buf)*KBUF + _row*QPITCH + _q*16,           \
                     Kh + (size_t)(_s0 + _row)*HD + _q*8);                     \
            else                                                               \
                cp16(sb + KS_OFF + (buf)*KBUF + _row*QPITCH + 128 + (_q-8)*16, \
                     Kl + (size_t)(_s0 + _row)*HD + (_q-8)*8);                 \
        }                                                                      \
        _Pragma("unroll")                                                      \
        for (int j = 0; j < 4; j++) {                                          \
            int _idx = tid + j*256;                                            \
            int _vr = _idx >> 3, _q = _idx & 7;                                \
            const __nv_bfloat16* _src = (_vr < 64)                             \
                ? Vh + (size_t)(_s0 + _vr)*HD + _q*8                           \
                : Vl + (size_t)(_s0 + _vr - 64)*HD + _q*8;                     \
            cp16(sb + VS_OFF + (buf)*VBUF + _vr*VPITCH + _q*16, _src);         \
        }                                                                      \
    } while (0)

    LOAD_KV(0, 0);
    CP_COMMIT();

    float oacc[4][4];
    #pragma unroll
    for (int j = 0; j < 4; j++)
        #pragma unroll
        for (int e = 0; e < 4; e++) oacc[j][e] = 0.0f;
    float mst[2] = {-1e30f, -1e30f};
    float lst[2] = {0.0f, 0.0f};

    float* redm = (float*)(sm + RED_OFF);
    float* reds = redm + 128;
    const int rbase = wm*16 + (lane >> 2);

    const int qoff_tab[6] = {0, 64, 128, 192, 0, 64};
    const int koff_tab[6] = {0, 64, 0, 64, 128, 192};

    for (int t = 0; t < 32; t++) {
        const int buf = t & 1;
        CP_WAIT(0);
        __syncthreads();
        if (t + 1 < 32) LOAD_KV(t + 1, buf ^ 1);
        CP_COMMIT();

        float sacc[4][4];
        #pragma unroll
        for (int j = 0; j < 4; j++)
            #pragma unroll
            for (int e = 0; e < 4; e++) sacc[j][e] = 0.0f;

        const uint32_t kb = sb + KS_OFF + buf*KBUF;
        #pragma unroll
        for (int kc = 0; kc < 6; kc++) {
            uint32_t bfr[4][4];
            #pragma unroll
            for (int nt = 0; nt < 4; nt++)
                ldsm4(bfr[nt], kb + (wn*32 + nt*8 + (lane & 7))*QPITCH
                               + koff_tab[kc] + (lane >> 3)*16);
            #pragma unroll
            for (int kk = 0; kk < 2; kk++) {
                uint32_t afr[4];
                ldsm4(afr, sb + QS_OFF + (wm*16 + (lane & 15))*QPITCH
                           + qoff_tab[kc] + kk*32 + (lane >> 4)*16);
                #pragma unroll
                for (int nt = 0; nt < 4; nt++)
                    mma_bf16(sacc[nt], afr, bfr[nt][kk*2], bfr[nt][kk*2+1]);
            }
        }

        #pragma unroll
        for (int rr = 0; rr < 2; rr++) {
            float mx = sacc[0][rr*2];
            #pragma unroll
            for (int nt = 0; nt < 4; nt++) {
                mx = fmaxf(mx, sacc[nt][rr*2]);
                mx = fmaxf(mx, sacc[nt][rr*2+1]);
            }
            mx = fmaxf(mx, __shfl_xor_sync(0xffffffffu, mx, 1));
            mx = fmaxf(mx, __shfl_xor_sync(0xffffffffu, mx, 2));
            if ((lane & 3) == 0)
                redm[wn*64 + rbase + rr*8] = mx;
        }
        __syncthreads();

        float alpha[2];
        #pragma unroll
        for (int rr = 0; rr < 2; rr++) {
            int row = rbase + rr*8;
            float rm = fmaxf(redm[row], redm[64 + row]);
            float mn = fmaxf(mst[rr], rm);
            alpha[rr] = ex2(mst[rr] - mn);
            mst[rr] = mn;
            float sum = 0.0f;
            #pragma unroll
            for (int nt = 0; nt < 4; nt++) {
                float p0 = ex2(sacc[nt][rr*2]   - mn);
                float p1 = ex2(sacc[nt][rr*2+1] - mn);
                sacc[nt][rr*2] = p0; sacc[nt][rr*2+1] = p1;
                sum += p0 + p1;
            }
            sum += __shfl_xor_sync(0xffffffffu, sum, 1);
            sum += __shfl_xor_sync(0xffffffffu, sum, 2);
            if ((lane & 3) == 0)
                reds[wn*64 + row] = sum;
        }

        #pragma unroll
        for (int rr = 0; rr < 2; rr++) {
            int row = rbase + rr*8;
            char* prow = sm + PS_OFF + row*QPITCH;
            #pragma unroll
            for (int nt = 0; nt < 4; nt++) {
                int klc = wn*32 + nt*8 + 2*(lane & 3);
                __nv_bfloat162 h2, l2;
                split2(sacc[nt][rr*2], sacc[nt][rr*2+1], h2, l2);
                *(__nv_bfloat162*)(prow + klc*2)       = h2;
                *(__nv_bfloat162*)(prow + 128 + klc*2) = l2;
            }
        }
        __syncthreads();

        #pragma unroll
        for (int rr = 0; rr < 2; rr++) {
            int row = rbase + rr*8;
            lst[rr] = lst[rr]*alpha[rr] + reds[row] + reds[64+row];
            #pragma unroll
            for (int nt = 0; nt < 4; nt++) {
                oacc[nt][rr*2]   *= alpha[rr];
                oacc[nt][rr*2+1] *= alpha[rr];
            }
        }

        const uint32_t vb = sb + VS_OFF + buf*VBUF;
        #pragma unroll
        for (int k16 = 0; k16 < 12; k16++) {
            int poff  = (k16 < 4) ? k16*32 : (k16 < 8) ? 128 + (k16-4)*32 : (k16-8)*32;
            int vbase = (k16 < 4) ? k16*16 : (k16 < 8) ? (k16-4)*16 : 64 + (k16-8)*16;
            uint32_t afr[4];
            ldsm4(afr, sb + PS_OFF + (wm*16 + (lane & 15))*QPITCH
                       + poff + (lane >> 4)*16);
            uint32_t bfr[2][4];
            #pragma unroll
            for (int ng = 0; ng < 2; ng++)
                ldsm4t(bfr[ng], vb + (vbase + (lane & 7) + ((lane >> 3) & 1)*8)*VPITCH
                                + (wn*32 + ng*16 + (lane >> 4)*8)*2);
            #pragma unroll
            for (int nt = 0; nt < 4; nt++) {
                int ng = nt >> 1, nh = nt & 1;
                mma_bf16(oacc[nt], afr, bfr[ng][nh*2], bfr[ng][nh*2+1]);
            }
        }
    }

    #pragma unroll
    for (int rr = 0; rr < 2; rr++) {
        float inv = 1.0f / lst[rr];
        int row = rbase + rr*8;
        size_t off0 = base + (size_t)(qt*64 + row)*HD;
        #pragma unroll
        for (int nt = 0; nt < 4; nt++) {
            int hd = wn*32 + nt*8 + 2*(lane & 3);
            __nv_bfloat162 h2, l2;
            split2(oacc[nt][rr*2]*inv, oacc[nt][rr*2+1]*inv, h2, l2);
            *(__nv_bfloat162*)(g_Oh + off0 + hd) = h2;
            *(__nv_bfloat162*)(g_Ol + off0 + hd) = l2;
        }
    }
}

// ---------------------------------------------------------------------------
extern "C" void kernel_launch(void* const* d_in, const int* in_sizes, int n_in,
                              void* d_out, int out_size)
{
    const float* x    = (const float*)d_in[0];
    const float* Wqkv = (const float*)d_in[1];
    const float* bqkv = (const float*)d_in[2];
    const float* Wo   = (const float*)d_in[3];
    const float* bo   = (const float*)d_in[4];
    float* out = (float*)d_out;

    cudaFuncSetAttribute(gemm_wide_kernel,
                         cudaFuncAttributeMaxDynamicSharedMemorySize, SMEM_GEMM2);
    cudaFuncSetAttribute(gemm_ext_kernel,
                         cudaFuncAttributeMaxDynamicSharedMemorySize, SMEM_GEMM);
    cudaFuncSetAttribute(attn_kernel,
                         cudaFuncAttributeMaxDynamicSharedMemorySize, SMEM_ATTN);

    __nv_bfloat16 *Xh, *Xl, *WqTh, *WqTl, *WoTh, *WoTl, *Oh, *Ol;
    cudaGetSymbolAddress((void**)&Xh,   g_Xh);
    cudaGetSymbolAddress((void**)&Xl,   g_Xl);
    cudaGetSymbolAddress((void**)&WqTh, g_WqTh);
    cudaGetSymbolAddress((void**)&WqTl, g_WqTl);
    cudaGetSymbolAddress((void**)&WoTh, g_WoTh);
    cudaGetSymbolAddress((void**)&WoTl, g_WoTl);
    cudaGetSymbolAddress((void**)&Oh,   g_Oh);
    cudaGetSymbolAddress((void**)&Ol,   g_Ol);

    prep_kernel<<<8192 + 3072 + 1024, 256>>>(x, Wqkv, Wo);

    gemm_wide_kernel<<<dim3(NQKV/256, MTOT/128), 256, SMEM_GEMM2>>>(
        Xh, Xl, WqTh, WqTl, bqkv);

    attn_kernel<<<dim3(SS/64, NHEADS), 256, SMEM_ATTN>>>();

    gemm_ext_kernel<<<dim3(DD/128, MTOT/128), 256, SMEM_GEMM>>>(
        Oh, Ol, WoTh, WoTl, bo, out);
}

// round 12
// speedup vs baseline: 1.3614x; 1.3614x over previous
#include <cuda_runtime.h>
#include <cuda_fp16.h>
#include <cstdint>
#include <math.h>

// Problem constants
#define BB 4
#define SS 2048
#define DD 1024
#define HH 16
#define HD 64
#define MTOT (BB*SS)      // 8192
#define NQKV (3*DD)       // 3072
#define NHEADS (BB*HH)    // 64

// Q pre-scale: 1/sqrt(64) * log2(e)  (softmax done in exp2 domain)
#define QSCALE 0.1803368801111204f

// ---------------------------------------------------------------------------
// Scratch (static device globals — allowed). All fp16 now.
// ---------------------------------------------------------------------------
__device__ __half g_Xh[(size_t)MTOT*DD];
__device__ __half g_Xl[(size_t)MTOT*DD];
__device__ __half g_WqTh[(size_t)NQKV*DD];
__device__ __half g_WqTl[(size_t)NQKV*DD];
__device__ __half g_WoTh[(size_t)DD*DD];
__device__ __half g_WoTl[(size_t)DD*DD];
__device__ __half g_Q [(size_t)NHEADS*SS*HD];   // single (scaled)
__device__ __half g_Kh[(size_t)NHEADS*SS*HD];
__device__ __half g_Kl[(size_t)NHEADS*SS*HD];
__device__ __half g_Vh[(size_t)NHEADS*SS*HD];
__device__ __half g_Vl[(size_t)NHEADS*SS*HD];
__device__ __half g_O [(size_t)MTOT*DD];        // single

// ---------------------------------------------------------------------------
// PTX helpers
// ---------------------------------------------------------------------------
__device__ __forceinline__ uint32_t smem_u32(const void* p) {
    uint32_t a;
    asm("{ .reg .u64 t; cvta.to.shared.u64 t, %1; cvt.u32.u64 %0, t; }"
        : "=r"(a) : "l"(p));
    return a;
}
__device__ __forceinline__ void cp16(uint32_t dst, const void* src) {
    asm volatile("cp.async.cg.shared.global [%0], [%1], 16;\n"
                 :: "r"(dst), "l"(src));
}
#define CP_COMMIT() asm volatile("cp.async.commit_group;\n" ::: "memory")
#define CP_WAIT(n)  asm volatile("cp.async.wait_group %0;\n" :: "n"(n) : "memory")

__device__ __forceinline__ void ldsm4(uint32_t* r, uint32_t addr) {
    asm volatile("ldmatrix.sync.aligned.m8n8.x4.shared.b16 {%0,%1,%2,%3}, [%4];\n"
                 : "=r"(r[0]), "=r"(r[1]), "=r"(r[2]), "=r"(r[3]) : "r"(addr));
}
__device__ __forceinline__ void ldsm4t(uint32_t* r, uint32_t addr) {
    asm volatile("ldmatrix.sync.aligned.m8n8.x4.trans.shared.b16 {%0,%1,%2,%3}, [%4];\n"
                 : "=r"(r[0]), "=r"(r[1]), "=r"(r[2]), "=r"(r[3]) : "r"(addr));
}
__device__ __forceinline__ void mma_f16(float* c, const uint32_t* a,
                                        uint32_t b0, uint32_t b1) {
    asm volatile(
        "mma.sync.aligned.m16n8k16.row.col.f32.f16.f16.f32 "
        "{%0,%1,%2,%3}, {%4,%5,%6,%7}, {%8,%9}, {%0,%1,%2,%3};\n"
        : "+f"(c[0]), "+f"(c[1]), "+f"(c[2]), "+f"(c[3])
        : "r"(a[0]), "r"(a[1]), "r"(a[2]), "r"(a[3]), "r"(b0), "r"(b1));
}
__device__ __forceinline__ float ex2(float x) {
    float y;
    asm("ex2.approx.ftz.f32 %0, %1;" : "=f"(y) : "f"(x));
    return y;
}
__device__ __forceinline__ __half2 pack2h(float x, float y) {
    return __halves2half2(__float2half_rn(x), __float2half_rn(y));
}
__device__ __forceinline__ void split2h(float x, float y,
                                        __half2& h2, __half2& l2) {
    __half hx = __float2half_rn(x);
    __half hy = __float2half_rn(y);
    h2 = __halves2half2(hx, hy);
    l2 = __halves2half2(__float2half_rn(x - __half2float(hx)),
                        __float2half_rn(y - __half2float(hy)));
}

// ---------------------------------------------------------------------------
// Fused prep: X -> hi/lo fp16; Wqkv^T -> hi/lo fp16; Wo^T -> hi/lo fp16.
// ---------------------------------------------------------------------------
__device__ __forceinline__ void do_transpose_split(
    const float* __restrict__ W, int K, int N, int bx, int by, int tid,
    __half* __restrict__ Th, __half* __restrict__ Tl)
{
    __shared__ float t[32][33];
    int nb = bx * 32, kb = by * 32;
    int tx = tid & 31, ty = tid >> 5;
    #pragma unroll
    for (int j = 0; j < 4; j++)
        t[ty + j*8][tx] = W[(size_t)(kb + ty + j*8) * N + nb + tx];
    __syncthreads();
    #pragma unroll
    for (int j = 0; j < 4; j++) {
        int n = nb + ty + j*8;
        float v = t[tx][ty + j*8];
        __half h = __float2half_rn(v);
        Th[(size_t)n * K + kb + tx] = h;
        Tl[(size_t)n * K + kb + tx] = __float2half_rn(v - __half2float(h));
    }
}

__global__ void __launch_bounds__(256) prep_kernel(
    const float* __restrict__ x, const float* __restrict__ Wqkv,
    const float* __restrict__ Wo)
{
    int bid = blockIdx.x;
    int tid = threadIdx.x;
    if (bid < 8192) {
        size_t i4 = ((size_t)bid * 256 + tid) * 4;
        float4 v = *(const float4*)(x + i4);
        __half2 h0, l0, h1, l1;
        split2h(v.x, v.y, h0, l0);
        split2h(v.z, v.w, h1, l1);
        *(__half2*)(g_Xh + i4)     = h0;
        *(__half2*)(g_Xh + i4 + 2) = h1;
        *(__half2*)(g_Xl + i4)     = l0;
        *(__half2*)(g_Xl + i4 + 2) = l1;
    } else if (bid < 8192 + 3072) {
        int b = bid - 8192;
        do_transpose_split(Wqkv, DD, NQKV, b % 96, b / 96, tid, g_WqTh, g_WqTl);
    } else {
        int b = bid - 8192 - 3072;
        do_transpose_split(Wo, DD, DD, b % 32, b / 32, tid, g_WoTh, g_WoTl);
    }
}

// ---------------------------------------------------------------------------
// GEMM1: 3-pass fp16 ext-K (X pattern [h|l|h], W pattern [h|h|l]), BM=BN=128,
// BK=64/stage, 256 threads, 3-stage, 2 CTAs/SM. Epilogue: +bqkv, scatter:
// Q: *QSCALE -> single fp16; K,V: hi/lo fp16 split.
// ---------------------------------------------------------------------------
#define GPITCH 144
#define GSTG (128*GPITCH)
#define SMEM_GEMM (6*GSTG)

__global__ void __launch_bounds__(256, 2) gemm1_kernel(
    const __half* __restrict__ Ah, const __half* __restrict__ Al,
    const __half* __restrict__ Bh, const __half* __restrict__ Bl,
    const float* __restrict__ bias)
{
    extern __shared__ char sm[];
    const uint32_t sb = smem_u32(sm);
    const int tid = threadIdx.x, wid = tid >> 5, lane = tid & 31;
    const int wm = wid >> 2, wn = wid & 3;
    const int m0 = blockIdx.y * 128, n0 = blockIdx.x * 128;

    float acc[4][4][4];
    #pragma unroll
    for (int i = 0; i < 4; i++)
        #pragma unroll
        for (int j = 0; j < 4; j++)
            #pragma unroll
            for (int e = 0; e < 4; e++) acc[i][j][e] = 0.0f;

    #define G1_ISSUE(c, st) do {                                               \
        int _p = (c) >> 4; int _kb = ((c) & 15) * 64;                          \
        const __half* _Ap = (_p == 1) ? Al : Ah;                               \
        const __half* _Bp = (_p == 2) ? Bl : Bh;                               \
        uint32_t _da = sb + (st) * GSTG;                                       \
        uint32_t _db = sb + 3*GSTG + (st) * GSTG;                              \
        _Pragma("unroll")                                                      \
        for (int _j = 0; _j < 4; _j++) {                                       \
            int _idx = tid + _j*256;                                           \
            int _row = _idx >> 3, _q = _idx & 7;                               \
            cp16(_da + _row*GPITCH + _q*16,                                    \
                 _Ap + (size_t)(m0+_row)*DD + _kb + _q*8);                     \
            cp16(_db + _row*GPITCH + _q*16,                                    \
                 _Bp + (size_t)(n0+_row)*DD + _kb + _q*8);                     \
        }                                                                      \
    } while (0)

    G1_ISSUE(0, 0); CP_COMMIT();
    G1_ISSUE(1, 1); CP_COMMIT();

    const int NCH = 48;  // 3072 / 64
    int cur = 0;
    for (int c = 0; c < NCH; c++) {
        CP_WAIT(1);
        __syncthreads();
        int nxt = cur + 2 >= 3 ? cur - 1 : cur + 2;
        if (c + 2 < NCH) G1_ISSUE(c + 2, nxt);
        CP_COMMIT();

        uint32_t da = sb + cur * GSTG;
        uint32_t db = sb + 3*GSTG + cur * GSTG;

        #pragma unroll
        for (int kc2 = 0; kc2 < 2; kc2++) {
            uint32_t bfr[4][4];
            #pragma unroll
            for (int nt = 0; nt < 4; nt++)
                ldsm4(bfr[nt], db + (wn*32 + nt*8 + (lane & 7))*GPITCH
                               + kc2*64 + (lane >> 3)*16);
            #pragma unroll
            for (int kk = 0; kk < 2; kk++) {
                uint32_t afr[4][4];
                #pragma unroll
                for (int mt = 0; mt < 4; mt++)
                    ldsm4(afr[mt], da + (wm*64 + mt*16 + (lane & 15))*GPITCH
                                   + kc2*64 + kk*32 + (lane >> 4)*16);
                #pragma unroll
                for (int mt = 0; mt < 4; mt++)
                    #pragma unroll
                    for (int nt = 0; nt < 4; nt++)
                        mma_f16(acc[mt][nt], afr[mt], bfr[nt][kk*2], bfr[nt][kk*2+1]);
            }
        }
        cur = cur + 1 >= 3 ? 0 : cur + 1;
    }

    #pragma unroll
    for (int mt = 0; mt < 4; mt++) {
        #pragma unroll
        for (int rr = 0; rr < 2; rr++) {
            int row = wm*64 + mt*16 + (lane >> 2) + rr*8;
            int m = m0 + row;
            int b = m >> 11, s = m & 2047;
            #pragma unroll
            for (int nt = 0; nt < 4; nt++) {
                int col = n0 + wn*32 + nt*8 + 2*(lane & 3);
                float v0 = acc[mt][nt][rr*2]   + bias[col];
                float v1 = acc[mt][nt][rr*2+1] + bias[col+1];
                int h = col / 192;
                int t = col - h*192;
                int which = t >> 6;
                int hd = t & 63;
                size_t off = (((size_t)b*HH + h)*SS + s)*HD + hd;
                if (which == 0) {
                    *(__half2*)(g_Q + off) = pack2h(v0*QSCALE, v1*QSCALE);
                } else {
                    __half2 h2, l2;
                    split2h(v0, v1, h2, l2);
                    __half* dh = (which == 1) ? g_Kh : g_Vh;
                    __half* dl = (which == 1) ? g_Kl : g_Vl;
                    *(__half2*)(dh + off) = h2;
                    *(__half2*)(dl + off) = l2;
                }
            }
        }
    }
}

// ---------------------------------------------------------------------------
// GEMM2: 2-pass ext-K 2048 (A = O single, B pattern [Woh | Wol]).
// Same pipeline structure, NCH=32.
// ---------------------------------------------------------------------------
__global__ void __launch_bounds__(256, 2) gemm2_kernel(
    const __half* __restrict__ A,
    const __half* __restrict__ Bh, const __half* __restrict__ Bl,
    const float* __restrict__ bias, float* __restrict__ out)
{
    extern __shared__ char sm[];
    const uint32_t sb = smem_u32(sm);
    const int tid = threadIdx.x, wid = tid >> 5, lane = tid & 31;
    const int wm = wid >> 2, wn = wid & 3;
    const int m0 = blockIdx.y * 128, n0 = blockIdx.x * 128;

    float acc[4][4][4];
    #pragma unroll
    for (int i = 0; i < 4; i++)
        #pragma unroll
        for (int j = 0; j < 4; j++)
            #pragma unroll
            for (int e = 0; e < 4; e++) acc[i][j][e] = 0.0f;

    #define G2_ISSUE(c, st) do {                                               \
        int _p = (c) >> 4; int _kb = ((c) & 15) * 64;                          \
        const __half* _Bp = _p ? Bl : Bh;                                      \
        uint32_t _da = sb + (st) * GSTG;                                       \
        uint32_t _db = sb + 3*GSTG + (st) * GSTG;                              \
        _Pragma("unroll")                                                      \
        for (int _j = 0; _j < 4; _j++) {                                       \
            int _idx = tid + _j*256;                                           \
            int _row = _idx >> 3, _q = _idx & 7;                               \
            cp16(_da + _row*GPITCH + _q*16,                                    \
                 A + (size_t)(m0+_row)*DD + _kb + _q*8);                       \
            cp16(_db + _row*GPITCH + _q*16,                                    \
                 _Bp + (size_t)(n0+_row)*DD + _kb + _q*8);                     \
        }                                                                      \
    } while (0)

    G2_ISSUE(0, 0); CP_COMMIT();
    G2_ISSUE(1, 1); CP_COMMIT();

    const int NCH = 32;  // 2048 / 64
    int cur = 0;
    for (int c = 0; c < NCH; c++) {
        CP_WAIT(1);
        __syncthreads();
        int nxt = cur + 2 >= 3 ? cur - 1 : cur + 2;
        if (c + 2 < NCH) G2_ISSUE(c + 2, nxt);
        CP_COMMIT();

        uint32_t da = sb + cur * GSTG;
        uint32_t db = sb + 3*GSTG + cur * GSTG;

        #pragma unroll
        for (int kc2 = 0; kc2 < 2; kc2++) {
            uint32_t bfr[4][4];
            #pragma unroll
            for (int nt = 0; nt < 4; nt++)
                ldsm4(bfr[nt], db + (wn*32 + nt*8 + (lane & 7))*GPITCH
                               + kc2*64 + (lane >> 3)*16);
            #pragma unroll
            for (int kk = 0; kk < 2; kk++) {
                uint32_t afr[4][4];
                #pragma unroll
                for (int mt = 0; mt < 4; mt++)
                    ldsm4(afr[mt], da + (wm*64 + mt*16 + (lane & 15))*GPITCH
                                   + kc2*64 + kk*32 + (lane >> 4)*16);
                #pragma unroll
                for (int mt = 0; mt < 4; mt++)
                    #pragma unroll
                    for (int nt = 0; nt < 4; nt++)
                        mma_f16(acc[mt][nt], afr[mt], bfr[nt][kk*2], bfr[nt][kk*2+1]);
            }
        }
        cur = cur + 1 >= 3 ? 0 : cur + 1;
    }

    #pragma unroll
    for (int mt = 0; mt < 4; mt++) {
        #pragma unroll
        for (int rr = 0; rr < 2; rr++) {
            int row = wm*64 + mt*16 + (lane >> 2) + rr*8;
            int m = m0 + row;
            #pragma unroll
            for (int nt = 0; nt < 4; nt++) {
                int col = n0 + wn*32 + nt*8 + 2*(lane & 3);
                float2 f2;
                f2.x = acc[mt][nt][rr*2]   + bias[col];
                f2.y = acc[mt][nt][rr*2+1] + bias[col+1];
                *(float2*)&out[(size_t)m*DD + col] = f2;
            }
        }
    }
}

// ---------------------------------------------------------------------------
// Flash attention fp16: QK 2-pass (Q single x K hi/lo, ext-K 128),
// PV 2-pass (P single x V hi/lo, ext-K 128). Structure = proven R10 kernel.
// ---------------------------------------------------------------------------
#define QPITCH 144                   // Q: 64 fp16 = 128B + pad
#define KPITCH 272                   // K: [Kh|Kl] 256B + pad
#define VPITCH 144
#define PPITCH 144                   // P single: 128B + pad
#define QS_OFF 0
#define KS_OFF 9216                  // Q: 64*144
#define KBUF   17408                 // 64*272
#define VS_OFF (KS_OFF + 2*KBUF)     // 44032
#define VBUF   18432                 // 128*144
#define PS_OFF (VS_OFF + 2*VBUF)     // 80896
#define RED_OFF (PS_OFF + 9216)      // 90112
#define SMEM_ATTN (RED_OFF + 1024)   // 91136

__global__ void __launch_bounds__(256, 2) attn_kernel()
{
    const int qt = blockIdx.x;   // 0..31
    const int bh = blockIdx.y;   // 0..63
    extern __shared__ char sm[];
    const uint32_t sb = smem_u32(sm);
    const int tid = threadIdx.x, wid = tid >> 5, lane = tid & 31;
    const int wm = wid >> 1, wn = wid & 1;

    const size_t base = (size_t)bh * SS * HD;
    const __half* Qg = g_Q  + base + (size_t)qt*64*HD;
    const __half* Kh = g_Kh + base;
    const __half* Kl = g_Kl + base;
    const __half* Vh = g_Vh + base;
    const __half* Vl = g_Vl + base;

    // ---- load Q single: 64 rows x 128B, pitch 144 ----
    #pragma unroll
    for (int j = 0; j < 2; j++) {
        int idx = tid + j*256;
        int row = idx >> 3, q = idx & 7;
        cp16(sb + QS_OFF + row*QPITCH + q*16, Qg + (size_t)row*HD + q*8);
    }

    #define LOAD_KV(t, buf) do {                                               \
        int _s0 = (t) * 64;                                                    \
        _Pragma("unroll")                                                      \
        for (int j = 0; j < 4; j++) {                                          \
            int _idx = tid + j*256;                                            \
            int _row = _idx >> 4, _q = _idx & 15;                              \
            if (_q < 8)                                                        \
                cp16(sb + KS_OFF + (buf)*KBUF + _row*KPITCH + _q*16,           \
                     Kh + (size_t)(_s0 + _row)*HD + _q*8);                     \
            else                                                               \
                cp16(sb + KS_OFF + (buf)*KBUF + _row*KPITCH + 128 + (_q-8)*16, \
                     Kl + (size_t)(_s0 + _row)*HD + (_q-8)*8);                 \
        }                                                                      \
        _Pragma("unroll")                                                      \
        for (int j = 0; j < 4; j++) {                                          \
            int _idx = tid + j*256;                                            \
            int _vr = _idx >> 3, _q = _idx & 7;                                \
            const __half* _src = (_vr < 64)                                    \
                ? Vh + (size_t)(_s0 + _vr)*HD + _q*8                           \
                : Vl + (size_t)(_s0 + _vr - 64)*HD + _q*8;                     \
            cp16(sb + VS_OFF + (buf)*VBUF + _vr*VPITCH + _q*16, _src);         \
        }                                                                      \
    } while (0)

    LOAD_KV(0, 0);
    CP_COMMIT();

    float oacc[4][4];
    #pragma unroll
    for (int j = 0; j < 4; j++)
        #pragma unroll
        for (int e = 0; e < 4; e++) oacc[j][e] = 0.0f;
    float mst[2] = {-1e30f, -1e30f};
    float lst[2] = {0.0f, 0.0f};

    float* redm = (float*)(sm + RED_OFF);
    float* reds = redm + 128;
    const int rbase = wm*16 + (lane >> 2);

    // QK pass maps: 4 kc x 32 ext-K: Q [h|h], K [h|l]
    const int qoff_tab[4] = {0, 64, 0, 64};
    const int koff_tab[4] = {0, 64, 128, 192};

    for (int t = 0; t < 32; t++) {
        const int buf = t & 1;
        CP_WAIT(0);
        __syncthreads();
        if (t + 1 < 32) LOAD_KV(t + 1, buf ^ 1);
        CP_COMMIT();

        // ---- S = Q . K_ext^T (ext-K 128) ----
        float sacc[4][4];
        #pragma unroll
        for (int j = 0; j < 4; j++)
            #pragma unroll
            for (int e = 0; e < 4; e++) sacc[j][e] = 0.0f;

        const uint32_t kb = sb + KS_OFF + buf*KBUF;
        #pragma unroll
        for (int kc = 0; kc < 4; kc++) {
            uint32_t bfr[4][4];
            #pragma unroll
            for (int nt = 0; nt < 4; nt++)
                ldsm4(bfr[nt], kb + (wn*32 + nt*8 + (lane & 7))*KPITCH
                               + koff_tab[kc] + (lane >> 3)*16);
            #pragma unroll
            for (int kk = 0; kk < 2; kk++) {
                uint32_t afr[4];
                ldsm4(afr, sb + QS_OFF + (wm*16 + (lane & 15))*QPITCH
                           + qoff_tab[kc] + kk*32 + (lane >> 4)*16);
                #pragma unroll
                for (int nt = 0; nt < 4; nt++)
                    mma_f16(sacc[nt], afr, bfr[nt][kk*2], bfr[nt][kk*2+1]);
            }
        }
        // NOTE: qoff covers 64B per kc? Q row = 128B; each kc consumes 32
        // ext-K = 64B; kk adds 32B inside → qoff_tab + kk*32 spans {0,32,64,96}
        // for kc 0-1 pass1 and repeats for kc 2-3 pass2. Correct.

        // ---- online softmax (exp2 domain) ----
        #pragma unroll
        for (int rr = 0; rr < 2; rr++) {
            float mx = sacc[0][rr*2];
            #pragma unroll
            for (int nt = 0; nt < 4; nt++) {
                mx = fmaxf(mx, sacc[nt][rr*2]);
                mx = fmaxf(mx, sacc[nt][rr*2+1]);
            }
            mx = fmaxf(mx, __shfl_xor_sync(0xffffffffu, mx, 1));
            mx = fmaxf(mx, __shfl_xor_sync(0xffffffffu, mx, 2));
            if ((lane & 3) == 0)
                redm[wn*64 + rbase + rr*8] = mx;
        }
        __syncthreads();

        float alpha[2];
        #pragma unroll
        for (int rr = 0; rr < 2; rr++) {
            int row = rbase + rr*8;
            float rm = fmaxf(redm[row], redm[64 + row]);
            float mn = fmaxf(mst[rr], rm);
            alpha[rr] = ex2(mst[rr] - mn);
            mst[rr] = mn;
            float sum = 0.0f;
            #pragma unroll
            for (int nt = 0; nt < 4; nt++) {
                float p0 = ex2(sacc[nt][rr*2]   - mn);
                float p1 = ex2(sacc[nt][rr*2+1] - mn);
                sacc[nt][rr*2] = p0; sacc[nt][rr*2+1] = p1;
                sum += p0 + p1;
            }
            sum += __shfl_xor_sync(0xffffffffu, sum, 1);
            sum += __shfl_xor_sync(0xffffffffu, sum, 2);
            if ((lane & 3) == 0)
                reds[wn*64 + row] = sum;
        }

        // write P single fp16 (pitch 144)
        #pragma unroll
        for (int rr = 0; rr < 2; rr++) {
            int row = rbase + rr*8;
            char* prow = sm + PS_OFF + row*PPITCH;
            #pragma unroll
            for (int nt = 0; nt < 4; nt++) {
                int klc = wn*32 + nt*8 + 2*(lane & 3);
                *(__half2*)(prow + klc*2) =
                    pack2h(sacc[nt][rr*2], sacc[nt][rr*2+1]);
            }
        }
        __syncthreads();

        // l update + O rescale
        #pragma unroll
        for (int rr = 0; rr < 2; rr++) {
            int row = rbase + rr*8;
            lst[rr] = lst[rr]*alpha[rr] + reds[row] + reds[64+row];
            #pragma unroll
            for (int nt = 0; nt < 4; nt++) {
                oacc[nt][rr*2]   *= alpha[rr];
                oacc[nt][rr*2+1] *= alpha[rr];
            }
        }

        // ---- O += P . V_ext (ext-K 128: P.Vh k16 0-3, P.Vl k16 4-7) ----
        const uint32_t vb = sb + VS_OFF + buf*VBUF;
        #pragma unroll
        for (int k16 = 0; k16 < 8; k16++) {
            int poff  = (k16 & 3) * 32;
            int vbase = (k16 < 4) ? k16*16 : 64 + (k16-4)*16;
            uint32_t afr[4];
            ldsm4(afr, sb + PS_OFF + (wm*16 + (lane & 15))*PPITCH
                       + poff + (lane >> 4)*16);
            uint32_t bfr[2][4];
            #pragma unroll
            for (int ng = 0; ng < 2; ng++)
                ldsm4t(bfr[ng], vb + (vbase + (lane & 7) + ((lane >> 3) & 1)*8)*VPITCH
                                + (wn*32 + ng*16 + (lane >> 4)*8)*2);
            #pragma unroll
            for (int nt = 0; nt < 4; nt++) {
                int ng = nt >> 1, nh = nt & 1;
                mma_f16(oacc[nt], afr, bfr[ng][nh*2], bfr[ng][nh*2+1]);
            }
        }
    }

    // ---- finalize: O/l, single fp16 store ----
    #pragma unroll
    for (int rr = 0; rr < 2; rr++) {
        float inv = 1.0f / lst[rr];
        int row = rbase + rr*8;
        size_t off0 = base + (size_t)(qt*64 + row)*HD;
        #pragma unroll
        for (int nt = 0; nt < 4; nt++) {
            int hd = wn*32 + nt*8 + 2*(lane & 3);
            *(__half2*)(g_O + off0 + hd) =
                pack2h(oacc[nt][rr*2]*inv, oacc[nt][rr*2+1]*inv);
        }
    }
}

// ---------------------------------------------------------------------------
extern "C" void kernel_launch(void* const* d_in, const int* in_sizes, int n_in,
                              void* d_out, int out_size)
{
    const float* x    = (const float*)d_in[0];
    const float* Wqkv = (const float*)d_in[1];
    const float* bqkv = (const float*)d_in[2];
    const float* Wo   = (const float*)d_in[3];
    const float* bo   = (const float*)d_in[4];
    float* out = (float*)d_out;

    cudaFuncSetAttribute(gemm1_kernel,
                         cudaFuncAttributeMaxDynamicSharedMemorySize, SMEM_GEMM);
    cudaFuncSetAttribute(gemm2_kernel,
                         cudaFuncAttributeMaxDynamicSharedMemorySize, SMEM_GEMM);
    cudaFuncSetAttribute(attn_kernel,
                         cudaFuncAttributeMaxDynamicSharedMemorySize, SMEM_ATTN);

    __half *Xh, *Xl, *WqTh, *WqTl, *WoTh, *WoTl, *O;
    cudaGetSymbolAddress((void**)&Xh,   g_Xh);
    cudaGetSymbolAddress((void**)&Xl,   g_Xl);
    cudaGetSymbolAddress((void**)&WqTh, g_WqTh);
    cudaGetSymbolAddress((void**)&WqTl, g_WqTl);
    cudaGetSymbolAddress((void**)&WoTh, g_WoTh);
    cudaGetSymbolAddress((void**)&WoTl, g_WoTl);
    cudaGetSymbolAddress((void**)&O,    g_O);

    prep_kernel<<<8192 + 3072 + 1024, 256>>>(x, Wqkv, Wo);

    gemm1_kernel<<<dim3(NQKV/128, MTOT/128), 256, SMEM_GEMM>>>(
        Xh, Xl, WqTh, WqTl, bqkv);

    attn_kernel<<<dim3(SS/64, NHEADS), 256, SMEM_ATTN>>>();

    gemm2_kernel<<<dim3(DD/128, MTOT/128), 256, SMEM_GEMM>>>(
        O, WoTh, WoTl, bo, out);
}

// round 13
// speedup vs baseline: 1.5832x; 1.1629x over previous
#include <cuda_runtime.h>
#include <cuda_fp16.h>
#include <cstdint>
#include <math.h>

// Problem constants
#define BB 4
#define SS 2048
#define DD 1024
#define HH 16
#define HD 64
#define MTOT (BB*SS)      // 8192
#define NQKV (3*DD)       // 3072
#define NHEADS (BB*HH)    // 64

// Q pre-scale: 1/sqrt(64) * log2(e)  (softmax done in exp2 domain)
#define QSCALE 0.1803368801111204f

// ---------------------------------------------------------------------------
// Scratch (static device globals — allowed). All fp16.
// ---------------------------------------------------------------------------
__device__ __half g_X [(size_t)MTOT*DD];        // single
__device__ __half g_WqTh[(size_t)NQKV*DD];
__device__ __half g_WqTl[(size_t)NQKV*DD];
__device__ __half g_WoTh[(size_t)DD*DD];
__device__ __half g_WoTl[(size_t)DD*DD];
__device__ __half g_Q [(size_t)NHEADS*SS*HD];   // single (scaled)
__device__ __half g_Kh[(size_t)NHEADS*SS*HD];
__device__ __half g_Kl[(size_t)NHEADS*SS*HD];
__device__ __half g_Vh[(size_t)NHEADS*SS*HD];
__device__ __half g_Vl[(size_t)NHEADS*SS*HD];
__device__ __half g_O [(size_t)MTOT*DD];        // single

// ---------------------------------------------------------------------------
// PTX helpers
// ---------------------------------------------------------------------------
__device__ __forceinline__ uint32_t smem_u32(const void* p) {
    uint32_t a;
    asm("{ .reg .u64 t; cvta.to.shared.u64 t, %1; cvt.u32.u64 %0, t; }"
        : "=r"(a) : "l"(p));
    return a;
}
__device__ __forceinline__ void cp16(uint32_t dst, const void* src) {
    asm volatile("cp.async.cg.shared.global [%0], [%1], 16;\n"
                 :: "r"(dst), "l"(src));
}
#define CP_COMMIT() asm volatile("cp.async.commit_group;\n" ::: "memory")
#define CP_WAIT(n)  asm volatile("cp.async.wait_group %0;\n" :: "n"(n) : "memory")

__device__ __forceinline__ void ldsm4(uint32_t* r, uint32_t addr) {
    asm volatile("ldmatrix.sync.aligned.m8n8.x4.shared.b16 {%0,%1,%2,%3}, [%4];\n"
                 : "=r"(r[0]), "=r"(r[1]), "=r"(r[2]), "=r"(r[3]) : "r"(addr));
}
__device__ __forceinline__ void ldsm4t(uint32_t* r, uint32_t addr) {
    asm volatile("ldmatrix.sync.aligned.m8n8.x4.trans.shared.b16 {%0,%1,%2,%3}, [%4];\n"
                 : "=r"(r[0]), "=r"(r[1]), "=r"(r[2]), "=r"(r[3]) : "r"(addr));
}
__device__ __forceinline__ void mma_f16(float* c, const uint32_t* a,
                                        uint32_t b0, uint32_t b1) {
    asm volatile(
        "mma.sync.aligned.m16n8k16.row.col.f32.f16.f16.f32 "
        "{%0,%1,%2,%3}, {%4,%5,%6,%7}, {%8,%9}, {%0,%1,%2,%3};\n"
        : "+f"(c[0]), "+f"(c[1]), "+f"(c[2]), "+f"(c[3])
        : "r"(a[0]), "r"(a[1]), "r"(a[2]), "r"(a[3]), "r"(b0), "r"(b1));
}
__device__ __forceinline__ float ex2(float x) {
    float y;
    asm("ex2.approx.ftz.f32 %0, %1;" : "=f"(y) : "f"(x));
    return y;
}
__device__ __forceinline__ __half2 pack2h(float x, float y) {
    return __halves2half2(__float2half_rn(x), __float2half_rn(y));
}
__device__ __forceinline__ void split2h(float x, float y,
                                        __half2& h2, __half2& l2) {
    __half hx = __float2half_rn(x);
    __half hy = __float2half_rn(y);
    h2 = __halves2half2(hx, hy);
    l2 = __halves2half2(__float2half_rn(x - __half2float(hx)),
                        __float2half_rn(y - __half2float(hy)));
}

// ---------------------------------------------------------------------------
// Fused prep: X -> single fp16; Wqkv^T, Wo^T -> hi/lo fp16.
// ---------------------------------------------------------------------------
__device__ __forceinline__ void do_transpose_split(
    const float* __restrict__ W, int K, int N, int bx, int by, int tid,
    __half* __restrict__ Th, __half* __restrict__ Tl)
{
    __shared__ float t[32][33];
    int nb = bx * 32, kb = by * 32;
    int tx = tid & 31, ty = tid >> 5;
    #pragma unroll
    for (int j = 0; j < 4; j++)
        t[ty + j*8][tx] = W[(size_t)(kb + ty + j*8) * N + nb + tx];
    __syncthreads();
    #pragma unroll
    for (int j = 0; j < 4; j++) {
        int n = nb + ty + j*8;
        float v = t[tx][ty + j*8];
        __half h = __float2half_rn(v);
        Th[(size_t)n * K + kb + tx] = h;
        Tl[(size_t)n * K + kb + tx] = __float2half_rn(v - __half2float(h));
    }
}

__global__ void __launch_bounds__(256) prep_kernel(
    const float* __restrict__ x, const float* __restrict__ Wqkv,
    const float* __restrict__ Wo)
{
    int bid = blockIdx.x;
    int tid = threadIdx.x;
    if (bid < 8192) {
        size_t i4 = ((size_t)bid * 256 + tid) * 4;
        float4 v = *(const float4*)(x + i4);
        *(__half2*)(g_X + i4)     = pack2h(v.x, v.y);
        *(__half2*)(g_X + i4 + 2) = pack2h(v.z, v.w);
    } else if (bid < 8192 + 3072) {
        int b = bid - 8192;
        do_transpose_split(Wqkv, DD, NQKV, b % 96, b / 96, tid, g_WqTh, g_WqTl);
    } else {
        int b = bid - 8192 - 3072;
        do_transpose_split(Wo, DD, DD, b % 32, b / 32, tid, g_WoTh, g_WoTl);
    }
}

// ---------------------------------------------------------------------------
// GEMM1: 2-pass ext-K 2048 (A = X single, B pattern [Wh | Wl]).
// BM=BN=128, BK=64/stage, 256 threads, 3-stage, 2 CTAs/SM.
// Epilogue: +bqkv; Q: *QSCALE single fp16; K,V: hi/lo split.
// ---------------------------------------------------------------------------
#define GPITCH 144
#define GSTG (128*GPITCH)
#define SMEM_GEMM (6*GSTG)

__global__ void __launch_bounds__(256, 2) gemm1_kernel(
    const __half* __restrict__ A,
    const __half* __restrict__ Bh, const __half* __restrict__ Bl,
    const float* __restrict__ bias)
{
    extern __shared__ char sm[];
    const uint32_t sb = smem_u32(sm);
    const int tid = threadIdx.x, wid = tid >> 5, lane = tid & 31;
    const int wm = wid >> 2, wn = wid & 3;
    const int m0 = blockIdx.y * 128, n0 = blockIdx.x * 128;

    float acc[4][4][4];
    #pragma unroll
    for (int i = 0; i < 4; i++)
        #pragma unroll
        for (int j = 0; j < 4; j++)
            #pragma unroll
            for (int e = 0; e < 4; e++) acc[i][j][e] = 0.0f;

    #define G1_ISSUE(c, st) do {                                               \
        int _p = (c) >> 4; int _kb = ((c) & 15) * 64;                          \
        const __half* _Bp = _p ? Bl : Bh;                                      \
        uint32_t _da = sb + (st) * GSTG;                                       \
        uint32_t _db = sb + 3*GSTG + (st) * GSTG;                              \
        _Pragma("unroll")                                                      \
        for (int _j = 0; _j < 4; _j++) {                                       \
            int _idx = tid + _j*256;                                           \
            int _row = _idx >> 3, _q = _idx & 7;                               \
            cp16(_da + _row*GPITCH + _q*16,                                    \
                 A + (size_t)(m0+_row)*DD + _kb + _q*8);                       \
            cp16(_db + _row*GPITCH + _q*16,                                    \
                 _Bp + (size_t)(n0+_row)*DD + _kb + _q*8);                     \
        }                                                                      \
    } while (0)

    G1_ISSUE(0, 0); CP_COMMIT();
    G1_ISSUE(1, 1); CP_COMMIT();

    const int NCH = 32;  // 2048 / 64
    int cur = 0;
    for (int c = 0; c < NCH; c++) {
        CP_WAIT(1);
        __syncthreads();
        int nxt = cur + 2 >= 3 ? cur - 1 : cur + 2;
        if (c + 2 < NCH) G1_ISSUE(c + 2, nxt);
        CP_COMMIT();

        uint32_t da = sb + cur * GSTG;
        uint32_t db = sb + 3*GSTG + cur * GSTG;

        #pragma unroll
        for (int kc2 = 0; kc2 < 2; kc2++) {
            uint32_t bfr[4][4];
            #pragma unroll
            for (int nt = 0; nt < 4; nt++)
                ldsm4(bfr[nt], db + (wn*32 + nt*8 + (lane & 7))*GPITCH
                               + kc2*64 + (lane >> 3)*16);
            #pragma unroll
            for (int kk = 0; kk < 2; kk++) {
                uint32_t afr[4][4];
                #pragma unroll
                for (int mt = 0; mt < 4; mt++)
                    ldsm4(afr[mt], da + (wm*64 + mt*16 + (lane & 15))*GPITCH
                                   + kc2*64 + kk*32 + (lane >> 4)*16);
                #pragma unroll
                for (int mt = 0; mt < 4; mt++)
                    #pragma unroll
                    for (int nt = 0; nt < 4; nt++)
                        mma_f16(acc[mt][nt], afr[mt], bfr[nt][kk*2], bfr[nt][kk*2+1]);
            }
        }
        cur = cur + 1 >= 3 ? 0 : cur + 1;
    }

    #pragma unroll
    for (int mt = 0; mt < 4; mt++) {
        #pragma unroll
        for (int rr = 0; rr < 2; rr++) {
            int row = wm*64 + mt*16 + (lane >> 2) + rr*8;
            int m = m0 + row;
            int b = m >> 11, s = m & 2047;
            #pragma unroll
            for (int nt = 0; nt < 4; nt++) {
                int col = n0 + wn*32 + nt*8 + 2*(lane & 3);
                float v0 = acc[mt][nt][rr*2]   + bias[col];
                float v1 = acc[mt][nt][rr*2+1] + bias[col+1];
                int h = col / 192;
                int t = col - h*192;
                int which = t >> 6;
                int hd = t & 63;
                size_t off = (((size_t)b*HH + h)*SS + s)*HD + hd;
                if (which == 0) {
                    *(__half2*)(g_Q + off) = pack2h(v0*QSCALE, v1*QSCALE);
                } else {
                    __half2 h2, l2;
                    split2h(v0, v1, h2, l2);
                    __half* dh = (which == 1) ? g_Kh : g_Vh;
                    __half* dl = (which == 1) ? g_Kl : g_Vl;
                    *(__half2*)(dh + off) = h2;
                    *(__half2*)(dl + off) = l2;
                }
            }
        }
    }
}

// ---------------------------------------------------------------------------
// GEMM2: 2-pass ext-K 2048 (A = O single, B pattern [Woh | Wol]).
// ---------------------------------------------------------------------------
__global__ void __launch_bounds__(256, 2) gemm2_kernel(
    const __half* __restrict__ A,
    const __half* __restrict__ Bh, const __half* __restrict__ Bl,
    const float* __restrict__ bias, float* __restrict__ out)
{
    extern __shared__ char sm[];
    const uint32_t sb = smem_u32(sm);
    const int tid = threadIdx.x, wid = tid >> 5, lane = tid & 31;
    const int wm = wid >> 2, wn = wid & 3;
    const int m0 = blockIdx.y * 128, n0 = blockIdx.x * 128;

    float acc[4][4][4];
    #pragma unroll
    for (int i = 0; i < 4; i++)
        #pragma unroll
        for (int j = 0; j < 4; j++)
            #pragma unroll
            for (int e = 0; e < 4; e++) acc[i][j][e] = 0.0f;

    #define G2_ISSUE(c, st) do {                                               \
        int _p = (c) >> 4; int _kb = ((c) & 15) * 64;                          \
        const __half* _Bp = _p ? Bl : Bh;                                      \
        uint32_t _da = sb + (st) * GSTG;                                       \
        uint32_t _db = sb + 3*GSTG + (st) * GSTG;                              \
        _Pragma("unroll")                                                      \
        for (int _j = 0; _j < 4; _j++) {                                       \
            int _idx = tid + _j*256;                                           \
            int _row = _idx >> 3, _q = _idx & 7;                               \
            cp16(_da + _row*GPITCH + _q*16,                                    \
                 A + (size_t)(m0+_row)*DD + _kb + _q*8);                       \
            cp16(_db + _row*GPITCH + _q*16,                                    \
                 _Bp + (size_t)(n0+_row)*DD + _kb + _q*8);                     \
        }                                                                      \
    } while (0)

    G2_ISSUE(0, 0); CP_COMMIT();
    G2_ISSUE(1, 1); CP_COMMIT();

    const int NCH = 32;  // 2048 / 64
    int cur = 0;
    for (int c = 0; c < NCH; c++) {
        CP_WAIT(1);
        __syncthreads();
        int nxt = cur + 2 >= 3 ? cur - 1 : cur + 2;
        if (c + 2 < NCH) G2_ISSUE(c + 2, nxt);
        CP_COMMIT();

        uint32_t da = sb + cur * GSTG;
        uint32_t db = sb + 3*GSTG + cur * GSTG;

        #pragma unroll
        for (int kc2 = 0; kc2 < 2; kc2++) {
            uint32_t bfr[4][4];
            #pragma unroll
            for (int nt = 0; nt < 4; nt++)
                ldsm4(bfr[nt], db + (wn*32 + nt*8 + (lane & 7))*GPITCH
                               + kc2*64 + (lane >> 3)*16);
            #pragma unroll
            for (int kk = 0; kk < 2; kk++) {
                uint32_t afr[4][4];
                #pragma unroll
                for (int mt = 0; mt < 4; mt++)
                    ldsm4(afr[mt], da + (wm*64 + mt*16 + (lane & 15))*GPITCH
                                   + kc2*64 + kk*32 + (lane >> 4)*16);
                #pragma unroll
                for (int mt = 0; mt < 4; mt++)
                    #pragma unroll
                    for (int nt = 0; nt < 4; nt++)
                        mma_f16(acc[mt][nt], afr[mt], bfr[nt][kk*2], bfr[nt][kk*2+1]);
            }
        }
        cur = cur + 1 >= 3 ? 0 : cur + 1;
    }

    #pragma unroll
    for (int mt = 0; mt < 4; mt++) {
        #pragma unroll
        for (int rr = 0; rr < 2; rr++) {
            int row = wm*64 + mt*16 + (lane >> 2) + rr*8;
            int m = m0 + row;
            #pragma unroll
            for (int nt = 0; nt < 4; nt++) {
                int col = n0 + wn*32 + nt*8 + 2*(lane & 3);
                float2 f2;
                f2.x = acc[mt][nt][rr*2]   + bias[col];
                f2.y = acc[mt][nt][rr*2+1] + bias[col+1];
                *(float2*)&out[(size_t)m*DD + col] = f2;
            }
        }
    }
}

// ---------------------------------------------------------------------------
// Flash attention fp16 (R12 proven): QK 2-pass (Q single x K hi/lo),
// PV 2-pass (P single x V hi/lo).
// ---------------------------------------------------------------------------
#define QPITCH 144
#define KPITCH 272
#define VPITCH 144
#define PPITCH 144
#define QS_OFF 0
#define KS_OFF 9216
#define KBUF   17408
#define VS_OFF (KS_OFF + 2*KBUF)
#define VBUF   18432
#define PS_OFF (VS_OFF + 2*VBUF)
#define RED_OFF (PS_OFF + 9216)
#define SMEM_ATTN (RED_OFF + 1024)

__global__ void __launch_bounds__(256, 2) attn_kernel()
{
    const int qt = blockIdx.x;
    const int bh = blockIdx.y;
    extern __shared__ char sm[];
    const uint32_t sb = smem_u32(sm);
    const int tid = threadIdx.x, wid = tid >> 5, lane = tid & 31;
    const int wm = wid >> 1, wn = wid & 1;

    const size_t base = (size_t)bh * SS * HD;
    const __half* Qg = g_Q  + base + (size_t)qt*64*HD;
    const __half* Kh = g_Kh + base;
    const __half* Kl = g_Kl + base;
    const __half* Vh = g_Vh + base;
    const __half* Vl = g_Vl + base;

    #pragma unroll
    for (int j = 0; j < 2; j++) {
        int idx = tid + j*256;
        int row = idx >> 3, q = idx & 7;
        cp16(sb + QS_OFF + row*QPITCH + q*16, Qg + (size_t)row*HD + q*8);
    }

    #define LOAD_KV(t, buf) do {                                               \
        int _s0 = (t) * 64;                                                    \
        _Pragma("unroll")                                                      \
        for (int j = 0; j < 4; j++) {                                          \
            int _idx = tid + j*256;                                            \
            int _row = _idx >> 4, _q = _idx & 15;                              \
            if (_q < 8)                                                        \
                cp16(sb + KS_OFF + (buf)*KBUF + _row*KPITCH + _q*16,           \
                     Kh + (size_t)(_s0 + _row)*HD + _q*8);                     \
            else                                                               \
                cp16(sb + KS_OFF + (buf)*KBUF + _row*KPITCH + 128 + (_q-8)*16, \
                     Kl + (size_t)(_s0 + _row)*HD + (_q-8)*8);                 \
        }                                                                      \
        _Pragma("unroll")                                                      \
        for (int j = 0; j < 4; j++) {                                          \
            int _idx = tid + j*256;                                            \
            int _vr = _idx >> 3, _q = _idx & 7;                                \
            const __half* _src = (_vr < 64)                                    \
                ? Vh + (size_t)(_s0 + _vr)*HD + _q*8                           \
                : Vl + (size_t)(_s0 + _vr - 64)*HD + _q*8;                     \
            cp16(sb + VS_OFF + (buf)*VBUF + _vr*VPITCH + _q*16, _src);         \
        }                                                                      \
    } while (0)

    LOAD_KV(0, 0);
    CP_COMMIT();

    float oacc[4][4];
    #pragma unroll
    for (int j = 0; j < 4; j++)
        #pragma unroll
        for (int e = 0; e < 4; e++) oacc[j][e] = 0.0f;
    float mst[2] = {-1e30f, -1e30f};
    float lst[2] = {0.0f, 0.0f};

    float* redm = (float*)(sm + RED_OFF);
    float* reds = redm + 128;
    const int rbase = wm*16 + (lane >> 2);

    const int qoff_tab[4] = {0, 64, 0, 64};
    const int koff_tab[4] = {0, 64, 128, 192};

    for (int t = 0; t < 32; t++) {
        const int buf = t & 1;
        CP_WAIT(0);
        __syncthreads();
        if (t + 1 < 32) LOAD_KV(t + 1, buf ^ 1);
        CP_COMMIT();

        float sacc[4][4];
        #pragma unroll
        for (int j = 0; j < 4; j++)
            #pragma unroll
            for (int e = 0; e < 4; e++) sacc[j][e] = 0.0f;

        const uint32_t kb = sb + KS_OFF + buf*KBUF;
        #pragma unroll
        for (int kc = 0; kc < 4; kc++) {
            uint32_t bfr[4][4];
            #pragma unroll
            for (int nt = 0; nt < 4; nt++)
                ldsm4(bfr[nt], kb + (wn*32 + nt*8 + (lane & 7))*KPITCH
                               + koff_tab[kc] + (lane >> 3)*16);
            #pragma unroll
            for (int kk = 0; kk < 2; kk++) {
                uint32_t afr[4];
                ldsm4(afr, sb + QS_OFF + (wm*16 + (lane & 15))*QPITCH
                           + qoff_tab[kc] + kk*32 + (lane >> 4)*16);
                #pragma unroll
                for (int nt = 0; nt < 4; nt++)
                    mma_f16(sacc[nt], afr, bfr[nt][kk*2], bfr[nt][kk*2+1]);
            }
        }

        #pragma unroll
        for (int rr = 0; rr < 2; rr++) {
            float mx = sacc[0][rr*2];
            #pragma unroll
            for (int nt = 0; nt < 4; nt++) {
                mx = fmaxf(mx, sacc[nt][rr*2]);
                mx = fmaxf(mx, sacc[nt][rr*2+1]);
            }
            mx = fmaxf(mx, __shfl_xor_sync(0xffffffffu, mx, 1));
            mx = fmaxf(mx, __shfl_xor_sync(0xffffffffu, mx, 2));
            if ((lane & 3) == 0)
                redm[wn*64 + rbase + rr*8] = mx;
        }
        __syncthreads();

        float alpha[2];
        #pragma unroll
        for (int rr = 0; rr < 2; rr++) {
            int row = rbase + rr*8;
            float rm = fmaxf(redm[row], redm[64 + row]);
            float mn = fmaxf(mst[rr], rm);
            alpha[rr] = ex2(mst[rr] - mn);
            mst[rr] = mn;
            float sum = 0.0f;
            #pragma unroll
            for (int nt = 0; nt < 4; nt++) {
                float p0 = ex2(sacc[nt][rr*2]   - mn);
                float p1 = ex2(sacc[nt][rr*2+1] - mn);
                sacc[nt][rr*2] = p0; sacc[nt][rr*2+1] = p1;
                sum += p0 + p1;
            }
            sum += __shfl_xor_sync(0xffffffffu, sum, 1);
            sum += __shfl_xor_sync(0xffffffffu, sum, 2);
            if ((lane & 3) == 0)
                reds[wn*64 + row] = sum;
        }

        #pragma unroll
        for (int rr = 0; rr < 2; rr++) {
            int row = rbase + rr*8;
            char* prow = sm + PS_OFF + row*PPITCH;
            #pragma unroll
            for (int nt = 0; nt < 4; nt++) {
                int klc = wn*32 + nt*8 + 2*(lane & 3);
                *(__half2*)(prow + klc*2) =
                    pack2h(sacc[nt][rr*2], sacc[nt][rr*2+1]);
            }
        }
        __syncthreads();

        #pragma unroll
        for (int rr = 0; rr < 2; rr++) {
            int row = rbase + rr*8;
            lst[rr] = lst[rr]*alpha[rr] + reds[row] + reds[64+row];
            #pragma unroll
            for (int nt = 0; nt < 4; nt++) {
                oacc[nt][rr*2]   *= alpha[rr];
                oacc[nt][rr*2+1] *= alpha[rr];
            }
        }

        const uint32_t vb = sb + VS_OFF + buf*VBUF;
        #pragma unroll
        for (int k16 = 0; k16 < 8; k16++) {
            int poff  = (k16 & 3) * 32;
            int vbase = (k16 < 4) ? k16*16 : 64 + (k16-4)*16;
            uint32_t afr[4];
            ldsm4(afr, sb + PS_OFF + (wm*16 + (lane & 15))*PPITCH
                       + poff + (lane >> 4)*16);
            uint32_t bfr[2][4];
            #pragma unroll
            for (int ng = 0; ng < 2; ng++)
                ldsm4t(bfr[ng], vb + (vbase + (lane & 7) + ((lane >> 3) & 1)*8)*VPITCH
                                + (wn*32 + ng*16 + (lane >> 4)*8)*2);
            #pragma unroll
            for (int nt = 0; nt < 4; nt++) {
                int ng = nt >> 1, nh = nt & 1;
                mma_f16(oacc[nt], afr, bfr[ng][nh*2], bfr[ng][nh*2+1]);
            }
        }
    }

    #pragma unroll
    for (int rr = 0; rr < 2; rr++) {
        float inv = 1.0f / lst[rr];
        int row = rbase + rr*8;
        size_t off0 = base + (size_t)(qt*64 + row)*HD;
        #pragma unroll
        for (int nt = 0; nt < 4; nt++) {
            int hd = wn*32 + nt*8 + 2*(lane & 3);
            *(__half2*)(g_O + off0 + hd) =
                pack2h(oacc[nt][rr*2]*inv, oacc[nt][rr*2+1]*inv);
        }
    }
}

// ---------------------------------------------------------------------------
extern "C" void kernel_launch(void* const* d_in, const int* in_sizes, int n_in,
                              void* d_out, int out_size)
{
    const float* x    = (const float*)d_in[0];
    const float* Wqkv = (const float*)d_in[1];
    const float* bqkv = (const float*)d_in[2];
    const float* Wo   = (const float*)d_in[3];
    const float* bo   = (const float*)d_in[4];
    float* out = (float*)d_out;

    cudaFuncSetAttribute(gemm1_kernel,
                         cudaFuncAttributeMaxDynamicSharedMemorySize, SMEM_GEMM);
    cudaFuncSetAttribute(gemm2_kernel,
                         cudaFuncAttributeMaxDynamicSharedMemorySize, SMEM_GEMM);
    cudaFuncSetAttribute(attn_kernel,
                         cudaFuncAttributeMaxDynamicSharedMemorySize, SMEM_ATTN);

    __half *X, *WqTh, *WqTl, *WoTh, *WoTl, *O;
    cudaGetSymbolAddress((void**)&X,    g_X);
    cudaGetSymbolAddress((void**)&WqTh, g_WqTh);
    cudaGetSymbolAddress((void**)&WqTl, g_WqTl);
    cudaGetSymbolAddress((void**)&WoTh, g_WoTh);
    cudaGetSymbolAddress((void**)&WoTl, g_WoTl);
    cudaGetSymbolAddress((void**)&O,    g_O);

    prep_kernel<<<8192 + 3072 + 1024, 256>>>(x, Wqkv, Wo);

    gemm1_kernel<<<dim3(NQKV/128, MTOT/128), 256, SMEM_GEMM>>>(
        X, WqTh, WqTl, bqkv);

    attn_kernel<<<dim3(SS/64, NHEADS), 256, SMEM_ATTN>>>();

    gemm2_kernel<<<dim3(DD/128, MTOT/128), 256, SMEM_GEMM>>>(
        O, WoTh, WoTl, bo, out);
}

// round 14
// speedup vs baseline: 2.5072x; 1.5836x over previous
#include <cuda_runtime.h>
#include <cuda_fp16.h>
#include <cstdint>
#include <math.h>

// Problem constants
#define BB 4
#define SS 2048
#define DD 1024
#define HH 16
#define HD 64
#define MTOT (BB*SS)      // 8192
#define NQKV (3*DD)       // 3072
#define NHEADS (BB*HH)    // 64

// Q pre-scale: 1/sqrt(64) * log2(e)  (softmax done in exp2 domain)
#define QSCALE 0.1803368801111204f

// ---------------------------------------------------------------------------
// Scratch (static device globals — allowed). All single fp16.
// ---------------------------------------------------------------------------
__device__ __half g_X  [(size_t)MTOT*DD];
__device__ __half g_WqT[(size_t)NQKV*DD];
__device__ __half g_WoT[(size_t)DD*DD];
__device__ __half g_Q  [(size_t)NHEADS*SS*HD];   // scaled
__device__ __half g_K  [(size_t)NHEADS*SS*HD];
__device__ __half g_V  [(size_t)NHEADS*SS*HD];
__device__ __half g_O  [(size_t)MTOT*DD];

// ---------------------------------------------------------------------------
// PTX helpers
// ---------------------------------------------------------------------------
__device__ __forceinline__ uint32_t smem_u32(const void* p) {
    uint32_t a;
    asm("{ .reg .u64 t; cvta.to.shared.u64 t, %1; cvt.u32.u64 %0, t; }"
        : "=r"(a) : "l"(p));
    return a;
}
__device__ __forceinline__ void cp16(uint32_t dst, const void* src) {
    asm volatile("cp.async.cg.shared.global [%0], [%1], 16;\n"
                 :: "r"(dst), "l"(src));
}
#define CP_COMMIT() asm volatile("cp.async.commit_group;\n" ::: "memory")
#define CP_WAIT(n)  asm volatile("cp.async.wait_group %0;\n" :: "n"(n) : "memory")

__device__ __forceinline__ void ldsm4(uint32_t* r, uint32_t addr) {
    asm volatile("ldmatrix.sync.aligned.m8n8.x4.shared.b16 {%0,%1,%2,%3}, [%4];\n"
                 : "=r"(r[0]), "=r"(r[1]), "=r"(r[2]), "=r"(r[3]) : "r"(addr));
}
__device__ __forceinline__ void ldsm4t(uint32_t* r, uint32_t addr) {
    asm volatile("ldmatrix.sync.aligned.m8n8.x4.trans.shared.b16 {%0,%1,%2,%3}, [%4];\n"
                 : "=r"(r[0]), "=r"(r[1]), "=r"(r[2]), "=r"(r[3]) : "r"(addr));
}
__device__ __forceinline__ void mma_f16(float* c, const uint32_t* a,
                                        uint32_t b0, uint32_t b1) {
    asm volatile(
        "mma.sync.aligned.m16n8k16.row.col.f32.f16.f16.f32 "
        "{%0,%1,%2,%3}, {%4,%5,%6,%7}, {%8,%9}, {%0,%1,%2,%3};\n"
        : "+f"(c[0]), "+f"(c[1]), "+f"(c[2]), "+f"(c[3])
        : "r"(a[0]), "r"(a[1]), "r"(a[2]), "r"(a[3]), "r"(b0), "r"(b1));
}
__device__ __forceinline__ float ex2(float x) {
    float y;
    asm("ex2.approx.ftz.f32 %0, %1;" : "=f"(y) : "f"(x));
    return y;
}
__device__ __forceinline__ __half2 pack2h(float x, float y) {
    return __halves2half2(__float2half_rn(x), __float2half_rn(y));
}

// ---------------------------------------------------------------------------
// Fused prep: X -> fp16; Wqkv^T, Wo^T -> fp16 (transpose + convert).
// ---------------------------------------------------------------------------
__device__ __forceinline__ void do_transpose_cvt(
    const float* __restrict__ W, int K, int N, int bx, int by, int tid,
    __half* __restrict__ T)
{
    __shared__ float t[32][33];
    int nb = bx * 32, kb = by * 32;
    int tx = tid & 31, ty = tid >> 5;
    #pragma unroll
    for (int j = 0; j < 4; j++)
        t[ty + j*8][tx] = W[(size_t)(kb + ty + j*8) * N + nb + tx];
    __syncthreads();
    #pragma unroll
    for (int j = 0; j < 4; j++) {
        int n = nb + ty + j*8;
        T[(size_t)n * K + kb + tx] = __float2half_rn(t[tx][ty + j*8]);
    }
}

__global__ void __launch_bounds__(256) prep_kernel(
    const float* __restrict__ x, const float* __restrict__ Wqkv,
    const float* __restrict__ Wo)
{
    int bid = blockIdx.x;
    int tid = threadIdx.x;
    if (bid < 8192) {
        size_t i4 = ((size_t)bid * 256 + tid) * 4;
        float4 v = *(const float4*)(x + i4);
        *(__half2*)(g_X + i4)     = pack2h(v.x, v.y);
        *(__half2*)(g_X + i4 + 2) = pack2h(v.z, v.w);
    } else if (bid < 8192 + 3072) {
        int b = bid - 8192;
        do_transpose_cvt(Wqkv, DD, NQKV, b % 96, b / 96, tid, g_WqT);
    } else {
        int b = bid - 8192 - 3072;
        do_transpose_cvt(Wo, DD, DD, b % 32, b / 32, tid, g_WoT);
    }
}

// ---------------------------------------------------------------------------
// GEMM1: plain fp16, K=1024 (NCH=16). BM=BN=128, BK=64/stage, 256 threads,
// 3-stage, 2 CTAs/SM. Epilogue: +bqkv; Q *QSCALE; all single fp16 scatter.
// ---------------------------------------------------------------------------
#define GPITCH 144
#define GSTG (128*GPITCH)
#define SMEM_GEMM (6*GSTG)

__global__ void __launch_bounds__(256, 2) gemm1_kernel(
    const __half* __restrict__ A, const __half* __restrict__ B,
    const float* __restrict__ bias)
{
    extern __shared__ char sm[];
    const uint32_t sb = smem_u32(sm);
    const int tid = threadIdx.x, wid = tid >> 5, lane = tid & 31;
    const int wm = wid >> 2, wn = wid & 3;
    const int m0 = blockIdx.y * 128, n0 = blockIdx.x * 128;

    float acc[4][4][4];
    #pragma unroll
    for (int i = 0; i < 4; i++)
        #pragma unroll
        for (int j = 0; j < 4; j++)
            #pragma unroll
            for (int e = 0; e < 4; e++) acc[i][j][e] = 0.0f;

    #define G1_ISSUE(c, st) do {                                               \
        int _kb = (c) * 64;                                                    \
        uint32_t _da = sb + (st) * GSTG;                                       \
        uint32_t _db = sb + 3*GSTG + (st) * GSTG;                              \
        _Pragma("unroll")                                                      \
        for (int _j = 0; _j < 4; _j++) {                                       \
            int _idx = tid + _j*256;                                           \
            int _row = _idx >> 3, _q = _idx & 7;                               \
            cp16(_da + _row*GPITCH + _q*16,                                    \
                 A + (size_t)(m0+_row)*DD + _kb + _q*8);                       \
            cp16(_db + _row*GPITCH + _q*16,                                    \
                 B + (size_t)(n0+_row)*DD + _kb + _q*8);                       \
        }                                                                      \
    } while (0)

    G1_ISSUE(0, 0); CP_COMMIT();
    G1_ISSUE(1, 1); CP_COMMIT();

    const int NCH = 16;  // 1024 / 64
    int cur = 0;
    for (int c = 0; c < NCH; c++) {
        CP_WAIT(1);
        __syncthreads();
        int nxt = cur + 2 >= 3 ? cur - 1 : cur + 2;
        if (c + 2 < NCH) G1_ISSUE(c + 2, nxt);
        CP_COMMIT();

        uint32_t da = sb + cur * GSTG;
        uint32_t db = sb + 3*GSTG + cur * GSTG;

        #pragma unroll
        for (int kc2 = 0; kc2 < 2; kc2++) {
            uint32_t bfr[4][4];
            #pragma unroll
            for (int nt = 0; nt < 4; nt++)
                ldsm4(bfr[nt], db + (wn*32 + nt*8 + (lane & 7))*GPITCH
                               + kc2*64 + (lane >> 3)*16);
            #pragma unroll
            for (int kk = 0; kk < 2; kk++) {
                uint32_t afr[4][4];
                #pragma unroll
                for (int mt = 0; mt < 4; mt++)
                    ldsm4(afr[mt], da + (wm*64 + mt*16 + (lane & 15))*GPITCH
                                   + kc2*64 + kk*32 + (lane >> 4)*16);
                #pragma unroll
                for (int mt = 0; mt < 4; mt++)
                    #pragma unroll
                    for (int nt = 0; nt < 4; nt++)
                        mma_f16(acc[mt][nt], afr[mt], bfr[nt][kk*2], bfr[nt][kk*2+1]);
            }
        }
        cur = cur + 1 >= 3 ? 0 : cur + 1;
    }

    #pragma unroll
    for (int mt = 0; mt < 4; mt++) {
        #pragma unroll
        for (int rr = 0; rr < 2; rr++) {
            int row = wm*64 + mt*16 + (lane >> 2) + rr*8;
            int m = m0 + row;
            int b = m >> 11, s = m & 2047;
            #pragma unroll
            for (int nt = 0; nt < 4; nt++) {
                int col = n0 + wn*32 + nt*8 + 2*(lane & 3);
                float v0 = acc[mt][nt][rr*2]   + bias[col];
                float v1 = acc[mt][nt][rr*2+1] + bias[col+1];
                int h = col / 192;
                int t = col - h*192;
                int which = t >> 6;
                int hd = t & 63;
                size_t off = (((size_t)b*HH + h)*SS + s)*HD + hd;
                if (which == 0) {
                    *(__half2*)(g_Q + off) = pack2h(v0*QSCALE, v1*QSCALE);
                } else {
                    __half* dst = (which == 1) ? g_K : g_V;
                    *(__half2*)(dst + off) = pack2h(v0, v1);
                }
            }
        }
    }
}

// ---------------------------------------------------------------------------
// GEMM2: plain fp16, K=1024 (NCH=16). Same structure, fp32 out.
// ---------------------------------------------------------------------------
__global__ void __launch_bounds__(256, 2) gemm2_kernel(
    const __half* __restrict__ A, const __half* __restrict__ B,
    const float* __restrict__ bias, float* __restrict__ out)
{
    extern __shared__ char sm[];
    const uint32_t sb = smem_u32(sm);
    const int tid = threadIdx.x, wid = tid >> 5, lane = tid & 31;
    const int wm = wid >> 2, wn = wid & 3;
    const int m0 = blockIdx.y * 128, n0 = blockIdx.x * 128;

    float acc[4][4][4];
    #pragma unroll
    for (int i = 0; i < 4; i++)
        #pragma unroll
        for (int j = 0; j < 4; j++)
            #pragma unroll
            for (int e = 0; e < 4; e++) acc[i][j][e] = 0.0f;

    G1_ISSUE(0, 0); CP_COMMIT();
    G1_ISSUE(1, 1); CP_COMMIT();

    const int NCH = 16;
    int cur = 0;
    for (int c = 0; c < NCH; c++) {
        CP_WAIT(1);
        __syncthreads();
        int nxt = cur + 2 >= 3 ? cur - 1 : cur + 2;
        if (c + 2 < NCH) G1_ISSUE(c + 2, nxt);
        CP_COMMIT();

        uint32_t da = sb + cur * GSTG;
        uint32_t db = sb + 3*GSTG + cur * GSTG;

        #pragma unroll
        for (int kc2 = 0; kc2 < 2; kc2++) {
            uint32_t bfr[4][4];
            #pragma unroll
            for (int nt = 0; nt < 4; nt++)
                ldsm4(bfr[nt], db + (wn*32 + nt*8 + (lane & 7))*GPITCH
                               + kc2*64 + (lane >> 3)*16);
            #pragma unroll
            for (int kk = 0; kk < 2; kk++) {
                uint32_t afr[4][4];
                #pragma unroll
                for (int mt = 0; mt < 4; mt++)
                    ldsm4(afr[mt], da + (wm*64 + mt*16 + (lane & 15))*GPITCH
                                   + kc2*64 + kk*32 + (lane >> 4)*16);
                #pragma unroll
                for (int mt = 0; mt < 4; mt++)
                    #pragma unroll
                    for (int nt = 0; nt < 4; nt++)
                        mma_f16(acc[mt][nt], afr[mt], bfr[nt][kk*2], bfr[nt][kk*2+1]);
            }
        }
        cur = cur + 1 >= 3 ? 0 : cur + 1;
    }

    #pragma unroll
    for (int mt = 0; mt < 4; mt++) {
        #pragma unroll
        for (int rr = 0; rr < 2; rr++) {
            int row = wm*64 + mt*16 + (lane >> 2) + rr*8;
            int m = m0 + row;
            #pragma unroll
            for (int nt = 0; nt < 4; nt++) {
                int col = n0 + wn*32 + nt*8 + 2*(lane & 3);
                float2 f2;
                f2.x = acc[mt][nt][rr*2]   + bias[col];
                f2.y = acc[mt][nt][rr*2+1] + bias[col+1];
                *(float2*)&out[(size_t)m*DD + col] = f2;
            }
        }
    }
}

// ---------------------------------------------------------------------------
// Flash attention, plain fp16: QK 1-pass (K=64), PV 1-pass (K=64).
// Structure identical to the proven R12/R13 kernel, halved pass counts.
// ---------------------------------------------------------------------------
#define APITCH 144
#define QS_OFF 0
#define KS_OFF 9216                  // Q: 64*144
#define KBUF   9216                  // K buf: 64*144
#define VS_OFF (KS_OFF + 2*KBUF)     // 27648
#define VBUF   9216                  // V buf: 64*144
#define PS_OFF (VS_OFF + 2*VBUF)     // 46080
#define RED_OFF (PS_OFF + 9216)      // 55296
#define SMEM_ATTN (RED_OFF + 1024)   // 56320

__global__ void __launch_bounds__(256, 2) attn_kernel()
{
    const int qt = blockIdx.x;   // 0..31
    const int bh = blockIdx.y;   // 0..63
    extern __shared__ char sm[];
    const uint32_t sb = smem_u32(sm);
    const int tid = threadIdx.x, wid = tid >> 5, lane = tid & 31;
    const int wm = wid >> 1, wn = wid & 1;

    const size_t base = (size_t)bh * SS * HD;
    const __half* Qg = g_Q + base + (size_t)qt*64*HD;
    const __half* Kg = g_K + base;
    const __half* Vg = g_V + base;

    // ---- load Q: 64 rows x 128B, pitch 144 ----
    #pragma unroll
    for (int j = 0; j < 2; j++) {
        int idx = tid + j*256;
        int row = idx >> 3, q = idx & 7;
        cp16(sb + QS_OFF + row*APITCH + q*16, Qg + (size_t)row*HD + q*8);
    }

    #define LOAD_KV(t, buf) do {                                               \
        int _s0 = (t) * 64;                                                    \
        _Pragma("unroll")                                                      \
        for (int j = 0; j < 2; j++) {                                          \
            int _idx = tid + j*256;                                            \
            int _row = _idx >> 3, _q = _idx & 7;                               \
            cp16(sb + KS_OFF + (buf)*KBUF + _row*APITCH + _q*16,               \
                 Kg + (size_t)(_s0 + _row)*HD + _q*8);                         \
            cp16(sb + VS_OFF + (buf)*VBUF + _row*APITCH + _q*16,               \
                 Vg + (size_t)(_s0 + _row)*HD + _q*8);                         \
        }                                                                      \
    } while (0)

    LOAD_KV(0, 0);
    CP_COMMIT();

    float oacc[4][4];
    #pragma unroll
    for (int j = 0; j < 4; j++)
        #pragma unroll
        for (int e = 0; e < 4; e++) oacc[j][e] = 0.0f;
    float mst[2] = {-1e30f, -1e30f};
    float lst[2] = {0.0f, 0.0f};

    float* redm = (float*)(sm + RED_OFF);
    float* reds = redm + 128;
    const int rbase = wm*16 + (lane >> 2);

    for (int t = 0; t < 32; t++) {
        const int buf = t & 1;
        CP_WAIT(0);
        __syncthreads();
        if (t + 1 < 32) LOAD_KV(t + 1, buf ^ 1);
        CP_COMMIT();

        // ---- S = Q . K^T (K = 64) ----
        float sacc[4][4];
        #pragma unroll
        for (int j = 0; j < 4; j++)
            #pragma unroll
            for (int e = 0; e < 4; e++) sacc[j][e] = 0.0f;

        const uint32_t kb = sb + KS_OFF + buf*KBUF;
        #pragma unroll
        for (int kc = 0; kc < 2; kc++) {
            uint32_t bfr[4][4];
            #pragma unroll
            for (int nt = 0; nt < 4; nt++)
                ldsm4(bfr[nt], kb + (wn*32 + nt*8 + (lane & 7))*APITCH
                               + kc*64 + (lane >> 3)*16);
            #pragma unroll
            for (int kk = 0; kk < 2; kk++) {
                uint32_t afr[4];
                ldsm4(afr, sb + QS_OFF + (wm*16 + (lane & 15))*APITCH
                           + kc*64 + kk*32 + (lane >> 4)*16);
                #pragma unroll
                for (int nt = 0; nt < 4; nt++)
                    mma_f16(sacc[nt], afr, bfr[nt][kk*2], bfr[nt][kk*2+1]);
            }
        }

        // ---- online softmax (exp2 domain) ----
        #pragma unroll
        for (int rr = 0; rr < 2; rr++) {
            float mx = sacc[0][rr*2];
            #pragma unroll
            for (int nt = 0; nt < 4; nt++) {
                mx = fmaxf(mx, sacc[nt][rr*2]);
                mx = fmaxf(mx, sacc[nt][rr*2+1]);
            }
            mx = fmaxf(mx, __shfl_xor_sync(0xffffffffu, mx, 1));
            mx = fmaxf(mx, __shfl_xor_sync(0xffffffffu, mx, 2));
            if ((lane & 3) == 0)
                redm[wn*64 + rbase + rr*8] = mx;
        }
        __syncthreads();

        float alpha[2];
        #pragma unroll
        for (int rr = 0; rr < 2; rr++) {
            int row = rbase + rr*8;
            float rm = fmaxf(redm[row], redm[64 + row]);
            float mn = fmaxf(mst[rr], rm);
            alpha[rr] = ex2(mst[rr] - mn);
            mst[rr] = mn;
            float sum = 0.0f;
            #pragma unroll
            for (int nt = 0; nt < 4; nt++) {
                float p0 = ex2(sacc[nt][rr*2]   - mn);
                float p1 = ex2(sacc[nt][rr*2+1] - mn);
                sacc[nt][rr*2] = p0; sacc[nt][rr*2+1] = p1;
                sum += p0 + p1;
            }
            sum += __shfl_xor_sync(0xffffffffu, sum, 1);
            sum += __shfl_xor_sync(0xffffffffu, sum, 2);
            if ((lane & 3) == 0)
                reds[wn*64 + row] = sum;
        }

        // write P fp16 (pitch 144)
        #pragma unroll
        for (int rr = 0; rr < 2; rr++) {
            int row = rbase + rr*8;
            char* prow = sm + PS_OFF + row*APITCH;
            #pragma unroll
            for (int nt = 0; nt < 4; nt++) {
                int klc = wn*32 + nt*8 + 2*(lane & 3);
                *(__half2*)(prow + klc*2) =
                    pack2h(sacc[nt][rr*2], sacc[nt][rr*2+1]);
            }
        }
        __syncthreads();

        // l update + O rescale
        #pragma unroll
        for (int rr = 0; rr < 2; rr++) {
            int row = rbase + rr*8;
            lst[rr] = lst[rr]*alpha[rr] + reds[row] + reds[64+row];
            #pragma unroll
            for (int nt = 0; nt < 4; nt++) {
                oacc[nt][rr*2]   *= alpha[rr];
                oacc[nt][rr*2+1] *= alpha[rr];
            }
        }

        // ---- O += P . V (K = 64 keys) ----
        const uint32_t vb = sb + VS_OFF + buf*VBUF;
        #pragma unroll
        for (int k16 = 0; k16 < 4; k16++) {
            uint32_t afr[4];
            ldsm4(afr, sb + PS_OFF + (wm*16 + (lane & 15))*APITCH
                       + k16*32 + (lane >> 4)*16);
            uint32_t bfr[2][4];
            #pragma unroll
            for (int ng = 0; ng < 2; ng++)
                ldsm4t(bfr[ng], vb + (k16*16 + (lane & 7) + ((lane >> 3) & 1)*8)*APITCH
                                + (wn*32 + ng*16 + (lane >> 4)*8)*2);
            #pragma unroll
            for (int nt = 0; nt < 4; nt++) {
                int ng = nt >> 1, nh = nt & 1;
                mma_f16(oacc[nt], afr, bfr[ng][nh*2], bfr[ng][nh*2+1]);
            }
        }
    }

    // ---- finalize ----
    #pragma unroll
    for (int rr = 0; rr < 2; rr++) {
        float inv = 1.0f / lst[rr];
        int row = rbase + rr*8;
        size_t off0 = base + (size_t)(qt*64 + row)*HD;
        #pragma unroll
        for (int nt = 0; nt < 4; nt++) {
            int hd = wn*32 + nt*8 + 2*(lane & 3);
            *(__half2*)(g_O + off0 + hd) =
                pack2h(oacc[nt][rr*2]*inv, oacc[nt][rr*2+1]*inv);
        }
    }
}

// ---------------------------------------------------------------------------
extern "C" void kernel_launch(void* const* d_in, const int* in_sizes, int n_in,
                              void* d_out, int out_size)
{
    const float* x    = (const float*)d_in[0];
    const float* Wqkv = (const float*)d_in[1];
    const float* bqkv = (const float*)d_in[2];
    const float* Wo   = (const float*)d_in[3];
    const float* bo   = (const float*)d_in[4];
    float* out = (float*)d_out;

    cudaFuncSetAttribute(gemm1_kernel,
                         cudaFuncAttributeMaxDynamicSharedMemorySize, SMEM_GEMM);
    cudaFuncSetAttribute(gemm2_kernel,
                         cudaFuncAttributeMaxDynamicSharedMemorySize, SMEM_GEMM);
    cudaFuncSetAttribute(attn_kernel,
                         cudaFuncAttributeMaxDynamicSharedMemorySize, SMEM_ATTN);

    __half *X, *WqT, *WoT, *O;
    cudaGetSymbolAddress((void**)&X,   g_X);
    cudaGetSymbolAddress((void**)&WqT, g_WqT);
    cudaGetSymbolAddress((void**)&WoT, g_WoT);
    cudaGetSymbolAddress((void**)&O,   g_O);

    prep_kernel<<<8192 + 3072 + 1024, 256>>>(x, Wqkv, Wo);

    gemm1_kernel<<<dim3(NQKV/128, MTOT/128), 256, SMEM_GEMM>>>(X, WqT, bqkv);

    attn_kernel<<<dim3(SS/64, NHEADS), 256, SMEM_ATTN>>>();

    gemm2_kernel<<<dim3(DD/128, MTOT/128), 256, SMEM_GEMM>>>(O, WoT, bo, out);
}

// round 15
// speedup vs baseline: 2.7997x; 1.1167x over previous
#include <cuda_runtime.h>
#include <cuda_fp16.h>
#include <cstdint>
#include <math.h>

// Problem constants
#define BB 4
#define SS 2048
#define DD 1024
#define HH 16
#define HD 64
#define MTOT (BB*SS)      // 8192
#define NQKV (3*DD)       // 3072
#define NHEADS (BB*HH)    // 64

// Q pre-scale: 1/sqrt(64) * log2(e)  (softmax done in exp2 domain)
#define QSCALE 0.1803368801111204f

// ---------------------------------------------------------------------------
// Scratch (static device globals — allowed). All single fp16.
// ---------------------------------------------------------------------------
__device__ __half g_X  [(size_t)MTOT*DD];
__device__ __half g_WqT[(size_t)NQKV*DD];
__device__ __half g_WoT[(size_t)DD*DD];
__device__ __half g_Q  [(size_t)NHEADS*SS*HD];   // scaled
__device__ __half g_K  [(size_t)NHEADS*SS*HD];
__device__ __half g_V  [(size_t)NHEADS*SS*HD];
__device__ __half g_O  [(size_t)MTOT*DD];

// ---------------------------------------------------------------------------
// PTX helpers
// ---------------------------------------------------------------------------
__device__ __forceinline__ uint32_t smem_u32(const void* p) {
    uint32_t a;
    asm("{ .reg .u64 t; cvta.to.shared.u64 t, %1; cvt.u32.u64 %0, t; }"
        : "=r"(a) : "l"(p));
    return a;
}
__device__ __forceinline__ void cp16(uint32_t dst, const void* src) {
    asm volatile("cp.async.cg.shared.global [%0], [%1], 16;\n"
                 :: "r"(dst), "l"(src));
}
#define CP_COMMIT() asm volatile("cp.async.commit_group;\n" ::: "memory")
#define CP_WAIT(n)  asm volatile("cp.async.wait_group %0;\n" :: "n"(n) : "memory")

__device__ __forceinline__ void ldsm4(uint32_t* r, uint32_t addr) {
    asm volatile("ldmatrix.sync.aligned.m8n8.x4.shared.b16 {%0,%1,%2,%3}, [%4];\n"
                 : "=r"(r[0]), "=r"(r[1]), "=r"(r[2]), "=r"(r[3]) : "r"(addr));
}
__device__ __forceinline__ void ldsm4t(uint32_t* r, uint32_t addr) {
    asm volatile("ldmatrix.sync.aligned.m8n8.x4.trans.shared.b16 {%0,%1,%2,%3}, [%4];\n"
                 : "=r"(r[0]), "=r"(r[1]), "=r"(r[2]), "=r"(r[3]) : "r"(addr));
}
__device__ __forceinline__ void mma_f16(float* c, const uint32_t* a,
                                        uint32_t b0, uint32_t b1) {
    asm volatile(
        "mma.sync.aligned.m16n8k16.row.col.f32.f16.f16.f32 "
        "{%0,%1,%2,%3}, {%4,%5,%6,%7}, {%8,%9}, {%0,%1,%2,%3};\n"
        : "+f"(c[0]), "+f"(c[1]), "+f"(c[2]), "+f"(c[3])
        : "r"(a[0]), "r"(a[1]), "r"(a[2]), "r"(a[3]), "r"(b0), "r"(b1));
}
__device__ __forceinline__ float ex2(float x) {
    float y;
    asm("ex2.approx.ftz.f32 %0, %1;" : "=f"(y) : "f"(x));
    return y;
}
__device__ __forceinline__ __half2 pack2h(float x, float y) {
    return __halves2half2(__float2half_rn(x), __float2half_rn(y));
}

// ---------------------------------------------------------------------------
// Fused prep: X -> fp16; Wqkv^T, Wo^T -> fp16.
// ---------------------------------------------------------------------------
__device__ __forceinline__ void do_transpose_cvt(
    const float* __restrict__ W, int K, int N, int bx, int by, int tid,
    __half* __restrict__ T)
{
    __shared__ float t[32][33];
    int nb = bx * 32, kb = by * 32;
    int tx = tid & 31, ty = tid >> 5;
    #pragma unroll
    for (int j = 0; j < 4; j++)
        t[ty + j*8][tx] = W[(size_t)(kb + ty + j*8) * N + nb + tx];
    __syncthreads();
    #pragma unroll
    for (int j = 0; j < 4; j++) {
        int n = nb + ty + j*8;
        T[(size_t)n * K + kb + tx] = __float2half_rn(t[tx][ty + j*8]);
    }
}

__global__ void __launch_bounds__(256) prep_kernel(
    const float* __restrict__ x, const float* __restrict__ Wqkv,
    const float* __restrict__ Wo)
{
    int bid = blockIdx.x;
    int tid = threadIdx.x;
    if (bid < 8192) {
        size_t i4 = ((size_t)bid * 256 + tid) * 4;
        float4 v = *(const float4*)(x + i4);
        *(__half2*)(g_X + i4)     = pack2h(v.x, v.y);
        *(__half2*)(g_X + i4 + 2) = pack2h(v.z, v.w);
    } else if (bid < 8192 + 3072) {
        int b = bid - 8192;
        do_transpose_cvt(Wqkv, DD, NQKV, b % 96, b / 96, tid, g_WqT);
    } else {
        int b = bid - 8192 - 3072;
        do_transpose_cvt(Wo, DD, DD, b % 32, b / 32, tid, g_WoT);
    }
}

// ---------------------------------------------------------------------------
// GEMM1: plain fp16, K=1024 (NCH=16). BM=BN=128, BK=64/stage, 256 threads,
// 3-stage, 2 CTAs/SM. Epilogue: +bqkv; Q *QSCALE; single fp16 scatter.
// ---------------------------------------------------------------------------
#define GPITCH 144
#define GSTG (128*GPITCH)
#define SMEM_GEMM (6*GSTG)

__global__ void __launch_bounds__(256, 2) gemm1_kernel(
    const __half* __restrict__ A, const __half* __restrict__ B,
    const float* __restrict__ bias)
{
    extern __shared__ char sm[];
    const uint32_t sb = smem_u32(sm);
    const int tid = threadIdx.x, wid = tid >> 5, lane = tid & 31;
    const int wm = wid >> 2, wn = wid & 3;
    const int m0 = blockIdx.y * 128, n0 = blockIdx.x * 128;

    float acc[4][4][4];
    #pragma unroll
    for (int i = 0; i < 4; i++)
        #pragma unroll
        for (int j = 0; j < 4; j++)
            #pragma unroll
            for (int e = 0; e < 4; e++) acc[i][j][e] = 0.0f;

    #define G1_ISSUE(c, st) do {                                               \
        int _kb = (c) * 64;                                                    \
        uint32_t _da = sb + (st) * GSTG;                                       \
        uint32_t _db = sb + 3*GSTG + (st) * GSTG;                              \
        _Pragma("unroll")                                                      \
        for (int _j = 0; _j < 4; _j++) {                                       \
            int _idx = tid + _j*256;                                           \
            int _row = _idx >> 3, _q = _idx & 7;                               \
            cp16(_da + _row*GPITCH + _q*16,                                    \
                 A + (size_t)(m0+_row)*DD + _kb + _q*8);                       \
            cp16(_db + _row*GPITCH + _q*16,                                    \
                 B + (size_t)(n0+_row)*DD + _kb + _q*8);                       \
        }                                                                      \
    } while (0)

    G1_ISSUE(0, 0); CP_COMMIT();
    G1_ISSUE(1, 1); CP_COMMIT();

    const int NCH = 16;
    int cur = 0;
    for (int c = 0; c < NCH; c++) {
        CP_WAIT(1);
        __syncthreads();
        int nxt = cur + 2 >= 3 ? cur - 1 : cur + 2;
        if (c + 2 < NCH) G1_ISSUE(c + 2, nxt);
        CP_COMMIT();

        uint32_t da = sb + cur * GSTG;
        uint32_t db = sb + 3*GSTG + cur * GSTG;

        #pragma unroll
        for (int kc2 = 0; kc2 < 2; kc2++) {
            uint32_t bfr[4][4];
            #pragma unroll
            for (int nt = 0; nt < 4; nt++)
                ldsm4(bfr[nt], db + (wn*32 + nt*8 + (lane & 7))*GPITCH
                               + kc2*64 + (lane >> 3)*16);
            #pragma unroll
            for (int kk = 0; kk < 2; kk++) {
                uint32_t afr[4][4];
                #pragma unroll
                for (int mt = 0; mt < 4; mt++)
                    ldsm4(afr[mt], da + (wm*64 + mt*16 + (lane & 15))*GPITCH
                                   + kc2*64 + kk*32 + (lane >> 4)*16);
                #pragma unroll
                for (int mt = 0; mt < 4; mt++)
                    #pragma unroll
                    for (int nt = 0; nt < 4; nt++)
                        mma_f16(acc[mt][nt], afr[mt], bfr[nt][kk*2], bfr[nt][kk*2+1]);
            }
        }
        cur = cur + 1 >= 3 ? 0 : cur + 1;
    }

    #pragma unroll
    for (int mt = 0; mt < 4; mt++) {
        #pragma unroll
        for (int rr = 0; rr < 2; rr++) {
            int row = wm*64 + mt*16 + (lane >> 2) + rr*8;
            int m = m0 + row;
            int b = m >> 11, s = m & 2047;
            #pragma unroll
            for (int nt = 0; nt < 4; nt++) {
                int col = n0 + wn*32 + nt*8 + 2*(lane & 3);
                float v0 = acc[mt][nt][rr*2]   + bias[col];
                float v1 = acc[mt][nt][rr*2+1] + bias[col+1];
                int h = col / 192;
                int t = col - h*192;
                int which = t >> 6;
                int hd = t & 63;
                size_t off = (((size_t)b*HH + h)*SS + s)*HD + hd;
                if (which == 0) {
                    *(__half2*)(g_Q + off) = pack2h(v0*QSCALE, v1*QSCALE);
                } else {
                    __half* dst = (which == 1) ? g_K : g_V;
                    *(__half2*)(dst + off) = pack2h(v0, v1);
                }
            }
        }
    }
}

// ---------------------------------------------------------------------------
// GEMM2: plain fp16, K=1024 (NCH=16). fp32 out.
// ---------------------------------------------------------------------------
__global__ void __launch_bounds__(256, 2) gemm2_kernel(
    const __half* __restrict__ A, const __half* __restrict__ B,
    const float* __restrict__ bias, float* __restrict__ out)
{
    extern __shared__ char sm[];
    const uint32_t sb = smem_u32(sm);
    const int tid = threadIdx.x, wid = tid >> 5, lane = tid & 31;
    const int wm = wid >> 2, wn = wid & 3;
    const int m0 = blockIdx.y * 128, n0 = blockIdx.x * 128;

    float acc[4][4][4];
    #pragma unroll
    for (int i = 0; i < 4; i++)
        #pragma unroll
        for (int j = 0; j < 4; j++)
            #pragma unroll
            for (int e = 0; e < 4; e++) acc[i][j][e] = 0.0f;

    G1_ISSUE(0, 0); CP_COMMIT();
    G1_ISSUE(1, 1); CP_COMMIT();

    const int NCH = 16;
    int cur = 0;
    for (int c = 0; c < NCH; c++) {
        CP_WAIT(1);
        __syncthreads();
        int nxt = cur + 2 >= 3 ? cur - 1 : cur + 2;
        if (c + 2 < NCH) G1_ISSUE(c + 2, nxt);
        CP_COMMIT();

        uint32_t da = sb + cur * GSTG;
        uint32_t db = sb + 3*GSTG + cur * GSTG;

        #pragma unroll
        for (int kc2 = 0; kc2 < 2; kc2++) {
            uint32_t bfr[4][4];
            #pragma unroll
            for (int nt = 0; nt < 4; nt++)
                ldsm4(bfr[nt], db + (wn*32 + nt*8 + (lane & 7))*GPITCH
                               + kc2*64 + (lane >> 3)*16);
            #pragma unroll
            for (int kk = 0; kk < 2; kk++) {
                uint32_t afr[4][4];
                #pragma unroll
                for (int mt = 0; mt < 4; mt++)
                    ldsm4(afr[mt], da + (wm*64 + mt*16 + (lane & 15))*GPITCH
                                   + kc2*64 + kk*32 + (lane >> 4)*16);
                #pragma unroll
                for (int mt = 0; mt < 4; mt++)
                    #pragma unroll
                    for (int nt = 0; nt < 4; nt++)
                        mma_f16(acc[mt][nt], afr[mt], bfr[nt][kk*2], bfr[nt][kk*2+1]);
            }
        }
        cur = cur + 1 >= 3 ? 0 : cur + 1;
    }

    #pragma unroll
    for (int mt = 0; mt < 4; mt++) {
        #pragma unroll
        for (int rr = 0; rr < 2; rr++) {
            int row = wm*64 + mt*16 + (lane >> 2) + rr*8;
            int m = m0 + row;
            #pragma unroll
            for (int nt = 0; nt < 4; nt++) {
                int col = n0 + wn*32 + nt*8 + 2*(lane & 3);
                float2 f2;
                f2.x = acc[mt][nt][rr*2]   + bias[col];
                f2.y = acc[mt][nt][rr*2+1] + bias[col+1];
                *(float2*)&out[(size_t)m*DD + col] = f2;
            }
        }
    }
}

// ---------------------------------------------------------------------------
// Flash attention fp16, KV tile = 128 (halved per-tile overhead):
// Q tile 64 rows, 16 KV tiles of 128 keys. Warp (wm,wn): QK keys wn*64..+64,
// PV cols wn*32..+32 over all 128 keys via smem P.
// ---------------------------------------------------------------------------
#define APITCH 144
#define PPITCH 272
#define QS_OFF 0
#define KS_OFF 9216                  // Q: 64*144
#define KBUF   18432                 // K buf: 128*144
#define VS_OFF (KS_OFF + 2*KBUF)     // 46080
#define VBUF   18432                 // V buf: 128*144
#define PS_OFF (VS_OFF + 2*VBUF)     // 82944
#define RED_OFF (PS_OFF + 64*PPITCH) // 100352
#define SMEM_ATTN (RED_OFF + 1024)   // 101376

__global__ void __launch_bounds__(256, 2) attn_kernel()
{
    const int qt = blockIdx.x;   // 0..31
    const int bh = blockIdx.y;   // 0..63
    extern __shared__ char sm[];
    const uint32_t sb = smem_u32(sm);
    const int tid = threadIdx.x, wid = tid >> 5, lane = tid & 31;
    const int wm = wid >> 1, wn = wid & 1;

    const size_t base = (size_t)bh * SS * HD;
    const __half* Qg = g_Q + base + (size_t)qt*64*HD;
    const __half* Kg = g_K + base;
    const __half* Vg = g_V + base;

    // ---- load Q: 64 rows x 128B, pitch 144 ----
    #pragma unroll
    for (int j = 0; j < 2; j++) {
        int idx = tid + j*256;
        int row = idx >> 3, q = idx & 7;
        cp16(sb + QS_OFF + row*APITCH + q*16, Qg + (size_t)row*HD + q*8);
    }

    #define LOAD_KV(t, buf) do {                                               \
        int _s0 = (t) * 128;                                                   \
        _Pragma("unroll")                                                      \
        for (int j = 0; j < 4; j++) {                                          \
            int _idx = tid + j*256;                                            \
            int _row = _idx >> 3, _q = _idx & 7;                               \
            cp16(sb + KS_OFF + (buf)*KBUF + _row*APITCH + _q*16,               \
                 Kg + (size_t)(_s0 + _row)*HD + _q*8);                         \
            cp16(sb + VS_OFF + (buf)*VBUF + _row*APITCH + _q*16,               \
                 Vg + (size_t)(_s0 + _row)*HD + _q*8);                         \
        }                                                                      \
    } while (0)

    LOAD_KV(0, 0);
    CP_COMMIT();

    float oacc[4][4];
    #pragma unroll
    for (int j = 0; j < 4; j++)
        #pragma unroll
        for (int e = 0; e < 4; e++) oacc[j][e] = 0.0f;
    float mst[2] = {-1e30f, -1e30f};
    float lst[2] = {0.0f, 0.0f};

    float* redm = (float*)(sm + RED_OFF);   // [2][64]
    float* reds = redm + 128;               // [2][64]
    const int rbase = wm*16 + (lane >> 2);

    for (int t = 0; t < 16; t++) {
        const int buf = t & 1;
        CP_WAIT(0);
        __syncthreads();
        if (t + 1 < 16) LOAD_KV(t + 1, buf ^ 1);
        CP_COMMIT();

        // ---- S = Q . K^T : warp covers keys wn*64..+64 (8 n-groups) ----
        float sacc[8][4];
        #pragma unroll
        for (int j = 0; j < 8; j++)
            #pragma unroll
            for (int e = 0; e < 4; e++) sacc[j][e] = 0.0f;

        const uint32_t kb = sb + KS_OFF + buf*KBUF;
        #pragma unroll
        for (int kc = 0; kc < 2; kc++) {
            uint32_t bfr[8][4];
            #pragma unroll
            for (int nt = 0; nt < 8; nt++)
                ldsm4(bfr[nt], kb + (wn*64 + nt*8 + (lane & 7))*APITCH
                               + kc*64 + (lane >> 3)*16);
            #pragma unroll
            for (int kk = 0; kk < 2; kk++) {
                uint32_t afr[4];
                ldsm4(afr, sb + QS_OFF + (wm*16 + (lane & 15))*APITCH
                           + kc*64 + kk*32 + (lane >> 4)*16);
                #pragma unroll
                for (int nt = 0; nt < 8; nt++)
                    mma_f16(sacc[nt], afr, bfr[nt][kk*2], bfr[nt][kk*2+1]);
            }
        }

        // ---- online softmax (exp2 domain), one update per 128 keys ----
        #pragma unroll
        for (int rr = 0; rr < 2; rr++) {
            float mx = sacc[0][rr*2];
            #pragma unroll
            for (int nt = 0; nt < 8; nt++) {
                mx = fmaxf(mx, sacc[nt][rr*2]);
                mx = fmaxf(mx, sacc[nt][rr*2+1]);
            }
            mx = fmaxf(mx, __shfl_xor_sync(0xffffffffu, mx, 1));
            mx = fmaxf(mx, __shfl_xor_sync(0xffffffffu, mx, 2));
            if ((lane & 3) == 0)
                redm[wn*64 + rbase + rr*8] = mx;
        }
        __syncthreads();

        float alpha[2];
        #pragma unroll
        for (int rr = 0; rr < 2; rr++) {
            int row = rbase + rr*8;
            float rm = fmaxf(redm[row], redm[64 + row]);
            float mn = fmaxf(mst[rr], rm);
            alpha[rr] = ex2(mst[rr] - mn);
            mst[rr] = mn;
            float sum = 0.0f;
            #pragma unroll
            for (int nt = 0; nt < 8; nt++) {
                float p0 = ex2(sacc[nt][rr*2]   - mn);
                float p1 = ex2(sacc[nt][rr*2+1] - mn);
                sacc[nt][rr*2] = p0; sacc[nt][rr*2+1] = p1;
                sum += p0 + p1;
            }
            sum += __shfl_xor_sync(0xffffffffu, sum, 1);
            sum += __shfl_xor_sync(0xffffffffu, sum, 2);
            if ((lane & 3) == 0)
                reds[wn*64 + row] = sum;
        }

        // write P fp16 (64 rows x 128 keys, pitch 272)
        #pragma unroll
        for (int rr = 0; rr < 2; rr++) {
            int row = rbase + rr*8;
            char* prow = sm + PS_OFF + row*PPITCH;
            #pragma unroll
            for (int nt = 0; nt < 8; nt++) {
                int klc = wn*64 + nt*8 + 2*(lane & 3);
                *(__half2*)(prow + klc*2) =
                    pack2h(sacc[nt][rr*2], sacc[nt][rr*2+1]);
            }
        }
        __syncthreads();

        // l update + O rescale (once per 128 keys)
        #pragma unroll
        for (int rr = 0; rr < 2; rr++) {
            int row = rbase + rr*8;
            lst[rr] = lst[rr]*alpha[rr] + reds[row] + reds[64+row];
            #pragma unroll
            for (int nt = 0; nt < 4; nt++) {
                oacc[nt][rr*2]   *= alpha[rr];
                oacc[nt][rr*2+1] *= alpha[rr];
            }
        }

        // ---- O += P . V over 128 keys (k16 0..7), HD cols wn*32..+32 ----
        const uint32_t vb = sb + VS_OFF + buf*VBUF;
        #pragma unroll
        for (int k16 = 0; k16 < 8; k16++) {
            uint32_t afr[4];
            ldsm4(afr, sb + PS_OFF + (wm*16 + (lane & 15))*PPITCH
                       + k16*32 + (lane >> 4)*16);
            uint32_t bfr[2][4];
            #pragma unroll
            for (int ng = 0; ng < 2; ng++)
                ldsm4t(bfr[ng], vb + (k16*16 + (lane & 7) + ((lane >> 3) & 1)*8)*APITCH
                                + (wn*32 + ng*16 + (lane >> 4)*8)*2);
            #pragma unroll
            for (int nt = 0; nt < 4; nt++) {
                int ng = nt >> 1, nh = nt & 1;
                mma_f16(oacc[nt], afr, bfr[ng][nh*2], bfr[ng][nh*2+1]);
            }
        }
    }

    // ---- finalize ----
    #pragma unroll
    for (int rr = 0; rr < 2; rr++) {
        float inv = 1.0f / lst[rr];
        int row = rbase + rr*8;
        size_t off0 = base + (size_t)(qt*64 + row)*HD;
        #pragma unroll
        for (int nt = 0; nt < 4; nt++) {
            int hd = wn*32 + nt*8 + 2*(lane & 3);
            *(__half2*)(g_O + off0 + hd) =
                pack2h(oacc[nt][rr*2]*inv, oacc[nt][rr*2+1]*inv);
        }
    }
}

// ---------------------------------------------------------------------------
extern "C" void kernel_launch(void* const* d_in, const int* in_sizes, int n_in,
                              void* d_out, int out_size)
{
    const float* x    = (const float*)d_in[0];
    const float* Wqkv = (const float*)d_in[1];
    const float* bqkv = (const float*)d_in[2];
    const float* Wo   = (const float*)d_in[3];
    const float* bo   = (const float*)d_in[4];
    float* out = (float*)d_out;

    cudaFuncSetAttribute(gemm1_kernel,
                         cudaFuncAttributeMaxDynamicSharedMemorySize, SMEM_GEMM);
    cudaFuncSetAttribute(gemm2_kernel,
                         cudaFuncAttributeMaxDynamicSharedMemorySize, SMEM_GEMM);
    cudaFuncSetAttribute(attn_kernel,
                         cudaFuncAttributeMaxDynamicSharedMemorySize, SMEM_ATTN);

    __half *X, *WqT, *WoT, *O;
    cudaGetSymbolAddress((void**)&X,   g_X);
    cudaGetSymbolAddress((void**)&WqT, g_WqT);
    cudaGetSymbolAddress((void**)&WoT, g_WoT);
    cudaGetSymbolAddress((void**)&O,   g_O);

    prep_kernel<<<8192 + 3072 + 1024, 256>>>(x, Wqkv, Wo);

    gemm1_kernel<<<dim3(NQKV/128, MTOT/128), 256, SMEM_GEMM>>>(X, WqT, bqkv);

    attn_kernel<<<dim3(SS/64, NHEADS), 256, SMEM_ATTN>>>();

    gemm2_kernel<<<dim3(DD/128, MTOT/128), 256, SMEM_GEMM>>>(O, WoT, bo, out);
}